// round 2
// baseline (speedup 1.0000x reference)
#include <cuda_runtime.h>
#include <math.h>

#define N_NODES 50000
#define IN_CH   128
#define HID     256
#define QKV_N   516            // 256 Q + 256 K + 4 vw
#define E_MAX   1600000

// ------------------------- scratch (device globals) -------------------------
__device__ float g_bufA[N_NODES * HID];
__device__ float g_bufB[N_NODES * HID];
__device__ float g_qkv [N_NODES * QKV_N];
__device__ float g_qkself[N_NODES * 4];
__device__ float g_dinv[N_NODES];
__device__ int   g_deg [N_NODES];
__device__ int   g_rowptr[N_NODES + 1];
__device__ int   g_cursor[N_NODES];
__device__ int   g_colsrc[E_MAX];
__device__ float g_Bqkv[HID * QKV_N];
__device__ float g_biasqkv[QKV_N];
__device__ float g_wsum[HID];
__device__ float g_bsum;

// ------------------------- small helpers -------------------------
__device__ __forceinline__ unsigned long long dup2(float v) {
    unsigned u = __float_as_uint(v);
    return ((unsigned long long)u << 32) | (unsigned long long)u;
}
__device__ __forceinline__ unsigned long long ffma2(unsigned long long a,
                                                    unsigned long long b,
                                                    unsigned long long c) {
    unsigned long long d;
    asm("fma.rn.f32x2 %0, %1, %2, %3;" : "=l"(d) : "l"(a), "l"(b), "l"(c));
    return d;
}

// ------------------------- weight prep -------------------------
// wsum[i] = sum_j out_proj_w[j,i]; bsum = sum(out_proj_b)
__global__ void k_wsum(const float* __restrict__ opw, const float* __restrict__ opb) {
    int i = threadIdx.x;        // 256 threads
    float s = 0.f;
    #pragma unroll 4
    for (int j = 0; j < HID; j++) s += opw[j * HID + i];
    g_wsum[i] = s;
    __shared__ float red[256];
    red[i] = opb[i];
    __syncthreads();
    for (int off = 128; off > 0; off >>= 1) {
        if (i < off) red[i] += red[i + off];
        __syncthreads();
    }
    if (i == 0) g_bsum = red[0];
}

// Packed B [K=256][N=516]: cols 0..511 = in_proj_w[j][k] (Q then K rows),
// cols 512..515 = per-head wsum-folded V columns. Bias likewise.
__global__ void k_pack(const float* __restrict__ ipw, const float* __restrict__ ipb) {
    int idx = blockIdx.x * blockDim.x + threadIdx.x;
    if (idx >= HID * QKV_N) return;
    int j = idx % QKV_N;
    int k = idx / QKV_N;
    float v;
    if (j < 512) {
        v = ipw[j * HID + k];
    } else {
        int h = j - 512;
        float s = 0.f;
        #pragma unroll 8
        for (int d = 0; d < 64; d++)
            s += g_wsum[h * 64 + d] * ipw[(512 + h * 64 + d) * HID + k];
        v = s;
    }
    g_Bqkv[k * QKV_N + j] = v;
    if (k == 0) {
        float b;
        if (j < 512) b = ipb[j];
        else {
            int h = j - 512;
            float s = 0.f;
            #pragma unroll 8
            for (int d = 0; d < 64; d++)
                s += g_wsum[h * 64 + d] * ipb[512 + h * 64 + d];
            b = s;
        }
        g_biasqkv[j] = b;
    }
}

// ------------------------- degree / CSR build -------------------------
__global__ void k_zero_deg() {
    int i = blockIdx.x * blockDim.x + threadIdx.x;
    if (i < N_NODES) g_deg[i] = 0;
}
__global__ void k_count(const int* __restrict__ ei, int E1) {
    int e = blockIdx.x * blockDim.x + threadIdx.x;
    if (e >= E1) return;
    int d = ei[E1 + e];
    atomicAdd(&g_deg[d], 1);
}
__global__ void k_dinv() {
    int i = blockIdx.x * blockDim.x + threadIdx.x;
    if (i < N_NODES) g_dinv[i] = rsqrtf((float)(g_deg[i] + 1));  // +1 self loop
}
// single-block exclusive scan of g_deg -> g_rowptr, cursor = rowptr start
__global__ void k_scan() {
    __shared__ int sh[1024];
    __shared__ int carry;
    int tid = threadIdx.x;
    if (tid == 0) { carry = 0; g_rowptr[0] = 0; }
    __syncthreads();
    for (int base = 0; base < N_NODES; base += 1024) {
        int i = base + tid;
        int v = (i < N_NODES) ? g_deg[i] : 0;
        sh[tid] = v;
        __syncthreads();
        for (int off = 1; off < 1024; off <<= 1) {
            int t = (tid >= off) ? sh[tid - off] : 0;
            __syncthreads();
            sh[tid] += t;
            __syncthreads();
        }
        if (i < N_NODES) {
            g_cursor[i]     = carry + sh[tid] - v;
            g_rowptr[i + 1] = carry + sh[tid];
        }
        __syncthreads();
        if (tid == 0) carry += sh[1023];
        __syncthreads();
    }
}
__global__ void k_scatter(const int* __restrict__ ei, int E1) {
    int e = blockIdx.x * blockDim.x + threadIdx.x;
    if (e >= E1) return;
    int s = ei[e];
    int d = ei[E1 + e];
    int pos = atomicAdd(&g_cursor[d], 1);
    g_colsrc[pos] = s;
}

// ------------------------- fp32 GEMM, f32x2 packed FMA -------------------------
// C[M,N] = A[M,K] @ B[K,N] + bias[N]
#define BM 128
#define BN 128
#define BKG 16
__global__ __launch_bounds__(256) void k_gemm(const float* __restrict__ A,
                                              const float* __restrict__ B,
                                              const float* __restrict__ bias,
                                              float* __restrict__ C,
                                              int M, int N, int K) {
    __shared__ unsigned long long As2[BKG][BM + 2];   // duplicated {a,a} pairs
    __shared__ float Bs[BKG][BN + 4];
    int tid = threadIdx.x;
    int tx = tid & 15, ty = tid >> 4;
    int m0 = blockIdx.y * BM, n0 = blockIdx.x * BN;

    unsigned long long acc[8][4];
    #pragma unroll
    for (int r = 0; r < 8; r++)
        #pragma unroll
        for (int c = 0; c < 4; c++) acc[r][c] = 0ull;

    for (int k0 = 0; k0 < K; k0 += BKG) {
        // load A tile (K is a multiple of 16; rows guarded)
        #pragma unroll
        for (int l = 0; l < 2; l++) {
            int lin = tid + l * 256;
            int row = lin >> 2, kv = lin & 3;
            int gr = m0 + row;
            float4 av = make_float4(0.f, 0.f, 0.f, 0.f);
            if (gr < M)
                av = *(const float4*)(A + (size_t)gr * K + k0 + kv * 4);
            As2[kv * 4 + 0][row] = dup2(av.x);
            As2[kv * 4 + 1][row] = dup2(av.y);
            As2[kv * 4 + 2][row] = dup2(av.z);
            As2[kv * 4 + 3][row] = dup2(av.w);
        }
        // load B tile (cols guarded for N=516)
        #pragma unroll
        for (int l = 0; l < 2; l++) {
            int lin = tid + l * 256;
            int kr = lin >> 5, nv = lin & 31;
            int gc = n0 + nv * 4;
            float4 bv = make_float4(0.f, 0.f, 0.f, 0.f);
            const float* Brow = B + (size_t)(k0 + kr) * N;
            if (gc + 3 < N) bv = *(const float4*)(Brow + gc);
            else {
                if (gc + 0 < N) bv.x = Brow[gc + 0];
                if (gc + 1 < N) bv.y = Brow[gc + 1];
                if (gc + 2 < N) bv.z = Brow[gc + 2];
            }
            Bs[kr][nv * 4 + 0] = bv.x;
            Bs[kr][nv * 4 + 1] = bv.y;
            Bs[kr][nv * 4 + 2] = bv.z;
            Bs[kr][nv * 4 + 3] = bv.w;
        }
        __syncthreads();
        #pragma unroll
        for (int kk = 0; kk < BKG; kk++) {
            unsigned long long af[8], bf[4];
            #pragma unroll
            for (int r = 0; r < 8; r++) af[r] = As2[kk][ty * 8 + r];
            #pragma unroll
            for (int c = 0; c < 4; c++)
                bf[c] = *(const unsigned long long*)&Bs[kk][tx * 8 + c * 2];
            #pragma unroll
            for (int r = 0; r < 8; r++)
                #pragma unroll
                for (int c = 0; c < 4; c++)
                    acc[r][c] = ffma2(af[r], bf[c], acc[r][c]);
        }
        __syncthreads();
    }
    // epilogue: unpack, add bias, guarded scalar stores
    #pragma unroll
    for (int r = 0; r < 8; r++) {
        int gr = m0 + ty * 8 + r;
        if (gr >= M) continue;
        float* Crow = C + (size_t)gr * N;
        #pragma unroll
        for (int c = 0; c < 4; c++) {
            int gc = n0 + tx * 8 + c * 2;
            float lo = __uint_as_float((unsigned)(acc[r][c] & 0xffffffffull));
            float hi = __uint_as_float((unsigned)(acc[r][c] >> 32));
            if (gc < N)     Crow[gc]     = lo + bias[gc];
            if (gc + 1 < N) Crow[gc + 1] = hi + bias[gc + 1];
        }
    }
}

// ------------------------- CSR aggregation (SpMM) -------------------------
// out[n] = dinv[n] * sum_{e: dst=n} dinv[src]*t[src] + dinv[n]^2 * t[n]   (+relu)
__global__ void k_agg(const float* __restrict__ tin, float* __restrict__ out, int relu) {
    int n = blockIdx.x;
    int t = threadIdx.x;                  // 64 threads, each owns 4 floats
    int beg = g_rowptr[n], end = g_rowptr[n + 1];
    const float4* tv = (const float4*)tin;
    float ax = 0.f, ay = 0.f, az = 0.f, aw = 0.f;
    #pragma unroll 4
    for (int j = beg; j < end; j++) {
        int s = g_colsrc[j];
        float w = g_dinv[s];
        float4 v = tv[(size_t)s * 64 + t];
        ax += w * v.x; ay += w * v.y; az += w * v.z; aw += w * v.w;
    }
    float d = g_dinv[n];
    float d2 = d * d;
    float4 sv = tv[(size_t)n * 64 + t];
    float4 r;
    r.x = d * ax + d2 * sv.x;
    r.y = d * ay + d2 * sv.y;
    r.z = d * az + d2 * sv.z;
    r.w = d * aw + d2 * sv.w;
    if (relu) {
        r.x = fmaxf(r.x, 0.f); r.y = fmaxf(r.y, 0.f);
        r.z = fmaxf(r.z, 0.f); r.w = fmaxf(r.w, 0.f);
    }
    ((float4*)out)[(size_t)n * 64 + t] = r;
}

// ------------------------- per-node Q.K self scores -------------------------
__global__ void k_qkself() {
    int w = (blockIdx.x * blockDim.x + threadIdx.x) >> 5;
    int lane = threadIdx.x & 31;
    if (w >= N_NODES) return;
    const float4* Q = (const float4*)(g_qkv + (size_t)w * QKV_N);
    const float4* Kp = (const float4*)(g_qkv + (size_t)w * QKV_N + 256);
    float4 q1 = Q[lane], k1 = Kp[lane];
    float4 q2 = Q[lane + 32], k2 = Kp[lane + 32];
    float d1 = q1.x * k1.x + q1.y * k1.y + q1.z * k1.z + q1.w * k1.w;
    float d2 = q2.x * k2.x + q2.y * k2.y + q2.z * k2.z + q2.w * k2.w;
    #pragma unroll
    for (int m = 1; m <= 8; m <<= 1) {
        d1 += __shfl_xor_sync(0xffffffffu, d1, m);
        d2 += __shfl_xor_sync(0xffffffffu, d2, m);
    }
    if (lane == 0)  { g_qkself[w * 4 + 0] = d1; g_qkself[w * 4 + 2] = d2; }
    if (lane == 16) { g_qkself[w * 4 + 1] = d1; g_qkself[w * 4 + 3] = d2; }
}

// ------------------------- per-prediction-edge attention -------------------------
__global__ void k_edge(const int* __restrict__ eip, float* __restrict__ out, int E2) {
    int w = (blockIdx.x * blockDim.x + threadIdx.x) >> 5;
    int lane = threadIdx.x & 31;
    if (w >= E2) return;
    int sp = eip[w];
    int dp = eip[E2 + w];
    const float4* Q = (const float4*)(g_qkv + (size_t)sp * QKV_N);
    const float4* Kp = (const float4*)(g_qkv + (size_t)dp * QKV_N + 256);
    float4 q1 = Q[lane], k1 = Kp[lane];
    float4 q2 = Q[lane + 32], k2 = Kp[lane + 32];
    float d1 = q1.x * k1.x + q1.y * k1.y + q1.z * k1.z + q1.w * k1.w;
    float d2 = q2.x * k2.x + q2.y * k2.y + q2.z * k2.z + q2.w * k2.w;
    #pragma unroll
    for (int m = 1; m <= 8; m <<= 1) {
        d1 += __shfl_xor_sync(0xffffffffu, d1, m);
        d2 += __shfl_xor_sync(0xffffffffu, d2, m);
    }
    // lanes 0..15 hold head0 (d1) & head2 (d2); lanes 16..31 hold head1 & head3
    float h1 = __shfl_sync(0xffffffffu, d1, 16);
    float h3 = __shfl_sync(0xffffffffu, d2, 16);
    if (lane == 0) {
        float s1[4] = { d1, h1, d2, h3 };     // cross scores q(sp).k(dp)
        const float* vws = g_qkv + (size_t)sp * QKV_N + 512;
        const float* vwd = g_qkv + (size_t)dp * QKV_N + 512;
        const float* qks = g_qkself + (size_t)sp * 4;
        float acc = g_bsum;
        #pragma unroll
        for (int h = 0; h < 4; h++) {
            // softmax over 2 keys: a0 = sigmoid((s0 - s1)*scale), scale = 1/8
            float a = 1.f / (1.f + expf((s1[h] - qks[h]) * 0.125f));
            acc += a * vws[h] + (1.f - a) * vwd[h];
        }
        out[w] = 1.f / (1.f + expf(-acc));
    }
}

// ------------------------- launch -------------------------
extern "C" void kernel_launch(void* const* d_in, const int* in_sizes, int n_in,
                              void* d_out, int out_size) {
    const float* x        = (const float*)d_in[0];
    const int* ei         = (const int*)d_in[1];
    const int* eip        = (const int*)d_in[2];
    const float* W1       = (const float*)d_in[3];
    const float* b1       = (const float*)d_in[4];
    const float* W2       = (const float*)d_in[5];
    const float* b2       = (const float*)d_in[6];
    const float* ipw      = (const float*)d_in[7];
    const float* ipb      = (const float*)d_in[8];
    const float* opw      = (const float*)d_in[9];
    const float* opb      = (const float*)d_in[10];
    float* out            = (float*)d_out;

    int E1 = in_sizes[1] / 2;
    int E2 = in_sizes[2] / 2;

    float *pA, *pB, *pQKV, *pBq, *pBias;
    cudaGetSymbolAddress((void**)&pA,    g_bufA);
    cudaGetSymbolAddress((void**)&pB,    g_bufB);
    cudaGetSymbolAddress((void**)&pQKV,  g_qkv);
    cudaGetSymbolAddress((void**)&pBq,   g_Bqkv);
    cudaGetSymbolAddress((void**)&pBias, g_biasqkv);

    // weight prep
    k_wsum<<<1, 256>>>(opw, opb);
    k_pack<<<(HID * QKV_N + 255) / 256, 256>>>(ipw, ipb);

    // degree + CSR
    k_zero_deg<<<(N_NODES + 255) / 256, 256>>>();
    k_count<<<(E1 + 255) / 256, 256>>>(ei, E1);
    k_dinv<<<(N_NODES + 255) / 256, 256>>>();
    k_scan<<<1, 1024>>>();
    k_scatter<<<(E1 + 255) / 256, 256>>>(ei, E1);

    // GCN layer 1
    k_gemm<<<dim3((HID + BN - 1) / BN, (N_NODES + BM - 1) / BM), 256>>>(
        x, W1, b1, pA, N_NODES, HID, IN_CH);
    k_agg<<<N_NODES, 64>>>(pA, pB, 1);

    // GCN layer 2
    k_gemm<<<dim3((HID + BN - 1) / BN, (N_NODES + BM - 1) / BM), 256>>>(
        pB, W2, b2, pA, N_NODES, HID, HID);
    k_agg<<<N_NODES, 64>>>(pA, pB, 0);

    // per-node QKV(+folded V) projection
    k_gemm<<<dim3((QKV_N + BN - 1) / BN, (N_NODES + BM - 1) / BM), 256>>>(
        pB, pBq, pBias, pQKV, N_NODES, QKV_N, HID);

    // self scores + per-edge attention
    k_qkself<<<(N_NODES * 32 + 255) / 256, 256>>>();
    k_edge<<<((size_t)E2 * 32 + 255) / 256, 256>>>(eip, out, E2);
}

// round 4
// speedup vs baseline: 1.6685x; 1.6685x over previous
#include <cuda_runtime.h>
#include <cuda_bf16.h>
#include <math.h>
#include <stdint.h>

#define N_NODES 50000
#define IN_CH   128
#define HID     256
#define QK_N    512
#define E_MAX   1600000

// ------------------------- scratch (device globals) -------------------------
__device__ float g_bufA[N_NODES * HID];          // GEMM outputs (pre-agg)
__device__ float g_bufB[N_NODES * HID];          // z (fp32, post-agg2)
__device__ float g_qkv [N_NODES * QK_N];         // Q(256) K(256) per node
__device__ float g_qkself[N_NODES * 4];
__device__ float g_vw[N_NODES * 4];
__device__ float g_dinv[N_NODES];
__device__ int   g_deg [N_NODES];
__device__ int   g_rowptr[N_NODES + 1];
__device__ int   g_cursor[N_NODES];
__device__ int   g_colsrc[E_MAX];

__device__ __nv_bfloat16 g_xh[N_NODES * IN_CH];
__device__ __nv_bfloat16 g_xl[N_NODES * IN_CH];
__device__ __nv_bfloat16 g_ah[N_NODES * HID];
__device__ __nv_bfloat16 g_al[N_NODES * HID];

__device__ __nv_bfloat16 g_w1h[HID * IN_CH];     // [N=256][K=128]
__device__ __nv_bfloat16 g_w1l[HID * IN_CH];
__device__ __nv_bfloat16 g_w2h[HID * HID];       // [N=256][K=256]
__device__ __nv_bfloat16 g_w2l[HID * HID];
__device__ __nv_bfloat16 g_wqkh[QK_N * HID];     // [N=512][K=256]
__device__ __nv_bfloat16 g_wqkl[QK_N * HID];
__device__ float g_biasqk[QK_N];
__device__ float g_wv[HID * 4];                  // folded V weights [k][h]
__device__ float g_bvw[4];
__device__ float g_wsum[HID];
__device__ float g_bsum;

// ------------------------- helpers -------------------------
__device__ __forceinline__ uint32_t smem_u32(const void* p) {
    uint32_t a;
    asm("{ .reg .u64 t; cvta.to.shared.u64 t, %1; cvt.u32.u64 %0, t; }" : "=r"(a) : "l"(p));
    return a;
}
__device__ __forceinline__ void ldsm_x4(uint32_t* r, uint32_t addr) {
    asm volatile("ldmatrix.sync.aligned.m8n8.x4.shared.b16 {%0,%1,%2,%3}, [%4];"
        : "=r"(r[0]), "=r"(r[1]), "=r"(r[2]), "=r"(r[3]) : "r"(addr));
}
__device__ __forceinline__ void ldsm_x2(uint32_t* r, uint32_t addr) {
    asm volatile("ldmatrix.sync.aligned.m8n8.x2.shared.b16 {%0,%1}, [%2];"
        : "=r"(r[0]), "=r"(r[1]) : "r"(addr));
}
__device__ __forceinline__ void mma_bf16(float* d, const uint32_t* a, const uint32_t* b) {
    asm volatile("mma.sync.aligned.m16n8k16.row.col.f32.bf16.bf16.f32 "
        "{%0,%1,%2,%3}, {%4,%5,%6,%7}, {%8,%9}, {%0,%1,%2,%3};"
        : "+f"(d[0]), "+f"(d[1]), "+f"(d[2]), "+f"(d[3])
        : "r"(a[0]), "r"(a[1]), "r"(a[2]), "r"(a[3]), "r"(b[0]), "r"(b[1]));
}
__device__ __forceinline__ void split_bf(float x, __nv_bfloat16& h, __nv_bfloat16& l) {
    h = __float2bfloat16_rn(x);
    l = __float2bfloat16_rn(x - __bfloat162float(h));
}

// ------------------------- weight prep -------------------------
__global__ void k_wsum(const float* __restrict__ opw, const float* __restrict__ opb) {
    int i = threadIdx.x;
    float s = 0.f;
    #pragma unroll 4
    for (int j = 0; j < HID; j++) s += opw[j * HID + i];
    g_wsum[i] = s;
    __shared__ float red[256];
    red[i] = opb[i];
    __syncthreads();
    for (int off = 128; off > 0; off >>= 1) {
        if (i < off) red[i] += red[i + off];
        __syncthreads();
    }
    if (i == 0) g_bsum = red[0];
}

__global__ void k_prep_qk(const float* __restrict__ ipw, const float* __restrict__ ipb) {
    int idx = blockIdx.x * blockDim.x + threadIdx.x;
    if (idx >= QK_N * HID) return;
    split_bf(ipw[idx], g_wqkh[idx], g_wqkl[idx]);
    if (idx < QK_N) g_biasqk[idx] = ipb[idx];
}

__global__ void k_prep_vw(const float* __restrict__ ipw, const float* __restrict__ ipb) {
    int idx = blockIdx.x * blockDim.x + threadIdx.x;
    if (idx >= HID * 4) return;
    int k = idx >> 2, h = idx & 3;
    float s = 0.f;
    #pragma unroll 8
    for (int d = 0; d < 64; d++)
        s += g_wsum[h * 64 + d] * ipw[(size_t)(512 + h * 64 + d) * HID + k];
    g_wv[k * 4 + h] = s;
    if (idx < 4) {
        float b = 0.f;
        for (int d = 0; d < 64; d++)
            b += g_wsum[idx * 64 + d] * ipb[512 + idx * 64 + d];
        g_bvw[idx] = b;
    }
}

__global__ void k_prep_w1(const float* __restrict__ W1) {
    int idx = blockIdx.x * blockDim.x + threadIdx.x;   // 256*128
    if (idx >= HID * IN_CH) return;
    int n = idx / IN_CH, k = idx % IN_CH;
    split_bf(W1[k * HID + n], g_w1h[idx], g_w1l[idx]);
}
__global__ void k_prep_w2(const float* __restrict__ W2) {
    int idx = blockIdx.x * blockDim.x + threadIdx.x;   // 256*256
    if (idx >= HID * HID) return;
    int n = idx / HID, k = idx % HID;
    split_bf(W2[k * HID + n], g_w2h[idx], g_w2l[idx]);
}
__global__ void k_cvt_x(const float* __restrict__ x) {
    int idx = blockIdx.x * blockDim.x + threadIdx.x;
    if (idx >= N_NODES * IN_CH) return;
    split_bf(x[idx], g_xh[idx], g_xl[idx]);
}

// ------------------------- degree / CSR build -------------------------
__global__ void k_zero_deg() {
    int i = blockIdx.x * blockDim.x + threadIdx.x;
    if (i < N_NODES) g_deg[i] = 0;
}
__global__ void k_count(const int* __restrict__ ei, int E1) {
    int e = blockIdx.x * blockDim.x + threadIdx.x;
    if (e >= E1) return;
    atomicAdd(&g_deg[ei[E1 + e]], 1);
}
__global__ void k_dinv() {
    int i = blockIdx.x * blockDim.x + threadIdx.x;
    if (i < N_NODES) g_dinv[i] = rsqrtf((float)(g_deg[i] + 1));
}
__global__ void k_scan() {
    __shared__ int sh[1024];
    __shared__ int carry;
    int tid = threadIdx.x;
    if (tid == 0) { carry = 0; g_rowptr[0] = 0; }
    __syncthreads();
    for (int base = 0; base < N_NODES; base += 1024) {
        int i = base + tid;
        int v = (i < N_NODES) ? g_deg[i] : 0;
        sh[tid] = v;
        __syncthreads();
        for (int off = 1; off < 1024; off <<= 1) {
            int t = (tid >= off) ? sh[tid - off] : 0;
            __syncthreads();
            sh[tid] += t;
            __syncthreads();
        }
        if (i < N_NODES) {
            g_cursor[i]     = carry + sh[tid] - v;
            g_rowptr[i + 1] = carry + sh[tid];
        }
        __syncthreads();
        if (tid == 0) carry += sh[1023];
        __syncthreads();
    }
}
__global__ void k_scatter(const int* __restrict__ ei, int E1) {
    int e = blockIdx.x * blockDim.x + threadIdx.x;
    if (e >= E1) return;
    int pos = atomicAdd(&g_cursor[ei[E1 + e]], 1);
    g_colsrc[pos] = ei[e];
}

// ------------------------- split-bf16 GEMM via mma.sync (HMMA) -------------------------
// C[M,N] = A[M,K] @ Bt[N,K]^T + bias ; split-precision: Ah*Bh + Al*Bh + Ah*Bl.
// CTA tile 128x128, 8 warps (64x32 each), kc=32 smem staging, ldmatrix fragments.
#define STR 40                 // padded smem row stride (bf16 elems), 80B: conflict-free ldmatrix
__global__ __launch_bounds__(256) void k_gemm_mma(
    const __nv_bfloat16* __restrict__ Ah, const __nv_bfloat16* __restrict__ Al,
    const __nv_bfloat16* __restrict__ Bh, const __nv_bfloat16* __restrict__ Bl,
    const float* __restrict__ bias, float* __restrict__ C,
    int M, int N, int K, int ldc)
{
    __shared__ __align__(16) __nv_bfloat16 sm[4][128][STR];  // Ah, Al, Bh, Bl
    const uint32_t TILE = 128 * STR * 2;

    int tid = threadIdx.x;
    int lane = tid & 31, w = tid >> 5;
    int wm0 = (w >> 2) * 64, wn0 = (w & 3) * 32;
    int m0 = blockIdx.y * 128, n0 = blockIdx.x * 128;

    float acc[4][4][4];
    #pragma unroll
    for (int mt = 0; mt < 4; mt++)
        #pragma unroll
        for (int nt = 0; nt < 4; nt++)
            #pragma unroll
            for (int q = 0; q < 4; q++) acc[mt][nt][q] = 0.f;

    uint32_t sbase = smem_u32(&sm[0][0][0]);
    int r8 = lane & 7, sel = lane >> 3;
    uint32_t aoff[4], boff[4];
    #pragma unroll
    for (int mt = 0; mt < 4; mt++)
        aoff[mt] = ((wm0 + mt * 16 + (sel & 1) * 8 + r8) * STR + (sel >> 1) * 8) * 2;
    int selb = sel & 1;
    #pragma unroll
    for (int nt = 0; nt < 4; nt++)
        boff[nt] = ((wn0 + nt * 8 + r8) * STR + selb * 8) * 2;

    for (int k0 = 0; k0 < K; k0 += 32) {
        // stage 4 tiles of [128][32] bf16; 2 uint4 per thread per tile
        #pragma unroll
        for (int i = 0; i < 2; i++) {
            int lin = tid + i * 256;
            int row = lin >> 2, seg = lin & 3;
            int gr = m0 + row;
            uint4 vh = make_uint4(0, 0, 0, 0), vl = make_uint4(0, 0, 0, 0);
            if (gr < M) {
                vh = *(const uint4*)(Ah + (size_t)gr * K + k0 + seg * 8);
                vl = *(const uint4*)(Al + (size_t)gr * K + k0 + seg * 8);
            }
            *(uint4*)&sm[0][row][seg * 8] = vh;
            *(uint4*)&sm[1][row][seg * 8] = vl;
            int gn = n0 + row;   // N is a multiple of 128
            *(uint4*)&sm[2][row][seg * 8] = *(const uint4*)(Bh + (size_t)gn * K + k0 + seg * 8);
            *(uint4*)&sm[3][row][seg * 8] = *(const uint4*)(Bl + (size_t)gn * K + k0 + seg * 8);
        }
        __syncthreads();
        #pragma unroll
        for (int ks = 0; ks < 2; ks++) {
            uint32_t ah[4][4], al[4][4], bh[4][2], bl[4][2];
            #pragma unroll
            for (int mt = 0; mt < 4; mt++) {
                ldsm_x4(ah[mt], sbase + 0 * TILE + aoff[mt] + ks * 32);
                ldsm_x4(al[mt], sbase + 1 * TILE + aoff[mt] + ks * 32);
            }
            #pragma unroll
            for (int nt = 0; nt < 4; nt++) {
                ldsm_x2(bh[nt], sbase + 2 * TILE + boff[nt] + ks * 32);
                ldsm_x2(bl[nt], sbase + 3 * TILE + boff[nt] + ks * 32);
            }
            #pragma unroll
            for (int mt = 0; mt < 4; mt++)
                #pragma unroll
                for (int nt = 0; nt < 4; nt++) {
                    mma_bf16(acc[mt][nt], ah[mt], bh[nt]);
                    mma_bf16(acc[mt][nt], al[mt], bh[nt]);
                    mma_bf16(acc[mt][nt], ah[mt], bl[nt]);
                }
        }
        __syncthreads();
    }

    // epilogue: c0,c1 at (row, col..col+1), c2,c3 at (row+8, ...)
    int g = lane >> 2, tg = lane & 3;
    #pragma unroll
    for (int mt = 0; mt < 4; mt++) {
        #pragma unroll
        for (int nt = 0; nt < 4; nt++) {
            int row = m0 + wm0 + mt * 16 + g;
            int col = n0 + wn0 + nt * 8 + tg * 2;
            float2 bv = *(const float2*)(bias + col);
            if (row < M) {
                float2 o0 = make_float2(acc[mt][nt][0] + bv.x, acc[mt][nt][1] + bv.y);
                *(float2*)(C + (size_t)row * ldc + col) = o0;
            }
            if (row + 8 < M) {
                float2 o1 = make_float2(acc[mt][nt][2] + bv.x, acc[mt][nt][3] + bv.y);
                *(float2*)(C + (size_t)(row + 8) * ldc + col) = o1;
            }
        }
    }
}

// ------------------------- CSR aggregation (SpMM) -------------------------
__global__ void k_agg(const float* __restrict__ tin, float* __restrict__ outf,
                      __nv_bfloat16* __restrict__ oh, __nv_bfloat16* __restrict__ ol,
                      int relu, int writef) {
    int n = blockIdx.x;
    int t = threadIdx.x;                  // 64 threads x 4 floats
    int beg = g_rowptr[n], end = g_rowptr[n + 1];
    const float4* tv = (const float4*)tin;
    float ax = 0.f, ay = 0.f, az = 0.f, aw = 0.f;
    #pragma unroll 4
    for (int j = beg; j < end; j++) {
        int s = g_colsrc[j];
        float w = g_dinv[s];
        float4 v = tv[(size_t)s * 64 + t];
        ax += w * v.x; ay += w * v.y; az += w * v.z; aw += w * v.w;
    }
    float d = g_dinv[n];
    float d2 = d * d;
    float4 sv = tv[(size_t)n * 64 + t];
    float4 r;
    r.x = d * ax + d2 * sv.x;
    r.y = d * ay + d2 * sv.y;
    r.z = d * az + d2 * sv.z;
    r.w = d * aw + d2 * sv.w;
    if (relu) {
        r.x = fmaxf(r.x, 0.f); r.y = fmaxf(r.y, 0.f);
        r.z = fmaxf(r.z, 0.f); r.w = fmaxf(r.w, 0.f);
    }
    if (writef) ((float4*)outf)[(size_t)n * 64 + t] = r;
    __nv_bfloat16 h0, l0, h1, l1, h2, l2, h3, l3;
    split_bf(r.x, h0, l0); split_bf(r.y, h1, l1);
    split_bf(r.z, h2, l2); split_bf(r.w, h3, l3);
    __nv_bfloat162* ph = (__nv_bfloat162*)oh;
    __nv_bfloat162* pl = (__nv_bfloat162*)ol;
    size_t base = (size_t)n * 128 + t * 2;
    ph[base]     = __nv_bfloat162(h0, h1);
    ph[base + 1] = __nv_bfloat162(h2, h3);
    pl[base]     = __nv_bfloat162(l0, l1);
    pl[base + 1] = __nv_bfloat162(l2, l3);
}

// ------------------------- per-node self scores + folded-V -------------------------
__global__ void k_qkself() {
    int w = (blockIdx.x * blockDim.x + threadIdx.x) >> 5;
    int lane = threadIdx.x & 31;
    if (w >= N_NODES) return;
    const float4* Q  = (const float4*)(g_qkv + (size_t)w * QK_N);
    const float4* Kp = (const float4*)(g_qkv + (size_t)w * QK_N + 256);
    float4 q1 = Q[lane], k1 = Kp[lane];
    float4 q2 = Q[lane + 32], k2 = Kp[lane + 32];
    float d1 = q1.x * k1.x + q1.y * k1.y + q1.z * k1.z + q1.w * k1.w;
    float d2 = q2.x * k2.x + q2.y * k2.y + q2.z * k2.z + q2.w * k2.w;
    #pragma unroll
    for (int m = 1; m <= 8; m <<= 1) {
        d1 += __shfl_xor_sync(0xffffffffu, d1, m);
        d2 += __shfl_xor_sync(0xffffffffu, d2, m);
    }
    if (lane == 0)  { g_qkself[w * 4 + 0] = d1; g_qkself[w * 4 + 2] = d2; }
    if (lane == 16) { g_qkself[w * 4 + 1] = d1; g_qkself[w * 4 + 3] = d2; }

    const float4* zr = (const float4*)(g_bufB + (size_t)w * HID);
    const float4* wv4 = (const float4*)g_wv;
    float p0 = 0.f, p1 = 0.f, p2 = 0.f, p3 = 0.f;
    #pragma unroll
    for (int half = 0; half < 2; half++) {
        float4 z = zr[lane + half * 32];
        int kb = (lane + half * 32) * 4;
        float4 w0 = wv4[kb], w1 = wv4[kb + 1], w2 = wv4[kb + 2], w3 = wv4[kb + 3];
        p0 += z.x * w0.x + z.y * w1.x + z.z * w2.x + z.w * w3.x;
        p1 += z.x * w0.y + z.y * w1.y + z.z * w2.y + z.w * w3.y;
        p2 += z.x * w0.z + z.y * w1.z + z.z * w2.z + z.w * w3.z;
        p3 += z.x * w0.w + z.y * w1.w + z.z * w2.w + z.w * w3.w;
    }
    #pragma unroll
    for (int m = 16; m > 0; m >>= 1) {
        p0 += __shfl_xor_sync(0xffffffffu, p0, m);
        p1 += __shfl_xor_sync(0xffffffffu, p1, m);
        p2 += __shfl_xor_sync(0xffffffffu, p2, m);
        p3 += __shfl_xor_sync(0xffffffffu, p3, m);
    }
    if (lane == 0) {
        g_vw[w * 4 + 0] = p0 + g_bvw[0];
        g_vw[w * 4 + 1] = p1 + g_bvw[1];
        g_vw[w * 4 + 2] = p2 + g_bvw[2];
        g_vw[w * 4 + 3] = p3 + g_bvw[3];
    }
}

// ------------------------- per-prediction-edge attention -------------------------
__global__ void k_edge(const int* __restrict__ eip, float* __restrict__ out, int E2) {
    int w = (blockIdx.x * blockDim.x + threadIdx.x) >> 5;
    int lane = threadIdx.x & 31;
    if (w >= E2) return;
    int sp = eip[w];
    int dp = eip[E2 + w];
    const float4* Q  = (const float4*)(g_qkv + (size_t)sp * QK_N);
    const float4* Kp = (const float4*)(g_qkv + (size_t)dp * QK_N + 256);
    float4 q1 = Q[lane], k1 = Kp[lane];
    float4 q2 = Q[lane + 32], k2 = Kp[lane + 32];
    float d1 = q1.x * k1.x + q1.y * k1.y + q1.z * k1.z + q1.w * k1.w;
    float d2 = q2.x * k2.x + q2.y * k2.y + q2.z * k2.z + q2.w * k2.w;
    #pragma unroll
    for (int m = 1; m <= 8; m <<= 1) {
        d1 += __shfl_xor_sync(0xffffffffu, d1, m);
        d2 += __shfl_xor_sync(0xffffffffu, d2, m);
    }
    float h1 = __shfl_sync(0xffffffffu, d1, 16);
    float h3 = __shfl_sync(0xffffffffu, d2, 16);
    if (lane == 0) {
        float s1[4] = { d1, h1, d2, h3 };
        const float* vws = g_vw + (size_t)sp * 4;
        const float* vwd = g_vw + (size_t)dp * 4;
        const float* qks = g_qkself + (size_t)sp * 4;
        float acc = g_bsum;
        #pragma unroll
        for (int h = 0; h < 4; h++) {
            float a = 1.f / (1.f + expf((s1[h] - qks[h]) * 0.125f));
            acc += a * vws[h] + (1.f - a) * vwd[h];
        }
        out[w] = 1.f / (1.f + expf(-acc));
    }
}

// ------------------------- launch -------------------------
extern "C" void kernel_launch(void* const* d_in, const int* in_sizes, int n_in,
                              void* d_out, int out_size) {
    const float* x   = (const float*)d_in[0];
    const int* ei    = (const int*)d_in[1];
    const int* eip   = (const int*)d_in[2];
    const float* W1  = (const float*)d_in[3];
    const float* b1  = (const float*)d_in[4];
    const float* W2  = (const float*)d_in[5];
    const float* b2  = (const float*)d_in[6];
    const float* ipw = (const float*)d_in[7];
    const float* ipb = (const float*)d_in[8];
    const float* opw = (const float*)d_in[9];
    const float* opb = (const float*)d_in[10];
    float* out       = (float*)d_out;

    int E1 = in_sizes[1] / 2;
    int E2 = in_sizes[2] / 2;

    float *pA, *pB, *pQKV, *pBqk;
    __nv_bfloat16 *pxh, *pxl, *pah, *pal, *pw1h, *pw1l, *pw2h, *pw2l, *pwqh, *pwql;
    cudaGetSymbolAddress((void**)&pA,   g_bufA);
    cudaGetSymbolAddress((void**)&pB,   g_bufB);
    cudaGetSymbolAddress((void**)&pQKV, g_qkv);
    cudaGetSymbolAddress((void**)&pBqk, g_biasqk);
    cudaGetSymbolAddress((void**)&pxh,  g_xh);
    cudaGetSymbolAddress((void**)&pxl,  g_xl);
    cudaGetSymbolAddress((void**)&pah,  g_ah);
    cudaGetSymbolAddress((void**)&pal,  g_al);
    cudaGetSymbolAddress((void**)&pw1h, g_w1h);
    cudaGetSymbolAddress((void**)&pw1l, g_w1l);
    cudaGetSymbolAddress((void**)&pw2h, g_w2h);
    cudaGetSymbolAddress((void**)&pw2l, g_w2l);
    cudaGetSymbolAddress((void**)&pwqh, g_wqkh);
    cudaGetSymbolAddress((void**)&pwql, g_wqkl);

    // weight prep + input conversion
    k_wsum<<<1, 256>>>(opw, opb);
    k_prep_qk<<<(QK_N * HID + 255) / 256, 256>>>(ipw, ipb);
    k_prep_vw<<<4, 256>>>(ipw, ipb);
    k_prep_w1<<<(HID * IN_CH + 255) / 256, 256>>>(W1);
    k_prep_w2<<<(HID * HID + 255) / 256, 256>>>(W2);
    k_cvt_x<<<(N_NODES * IN_CH + 255) / 256, 256>>>(x);

    // degree + CSR
    k_zero_deg<<<(N_NODES + 255) / 256, 256>>>();
    k_count<<<(E1 + 255) / 256, 256>>>(ei, E1);
    k_dinv<<<(N_NODES + 255) / 256, 256>>>();
    k_scan<<<1, 1024>>>();
    k_scatter<<<(E1 + 255) / 256, 256>>>(ei, E1);

    dim3 g1(HID / 128, (N_NODES + 127) / 128);
    dim3 g3(QK_N / 128, (N_NODES + 127) / 128);

    // GCN layer 1: h = relu(agg(x@W1+b1))
    k_gemm_mma<<<g1, 256>>>(pxh, pxl, pw1h, pw1l, b1, pA, N_NODES, HID, IN_CH, HID);
    k_agg<<<N_NODES, 64>>>(pA, nullptr, pah, pal, 1, 0);

    // GCN layer 2: z = agg(h@W2+b2)
    k_gemm_mma<<<g1, 256>>>(pah, pal, pw2h, pw2l, b2, pA, N_NODES, HID, HID, HID);
    k_agg<<<N_NODES, 64>>>(pA, pB, pah, pal, 0, 1);

    // QK projection (512 cols)
    k_gemm_mma<<<g3, 256>>>(pah, pal, pwqh, pwql, pBqk, pQKV, N_NODES, QK_N, HID, QK_N);

    // self scores + folded V, then per-edge attention
    k_qkself<<<(N_NODES * 32 + 255) / 256, 256>>>();
    k_edge<<<((size_t)E2 * 32 + 255) / 256, 256>>>(eip, out, E2);
}

// round 5
// speedup vs baseline: 1.8226x; 1.0923x over previous
#include <cuda_runtime.h>
#include <cuda_bf16.h>
#include <cuda_fp16.h>
#include <math.h>
#include <stdint.h>

#define N_NODES 50000
#define IN_CH   128
#define HID     256
#define QK_N    512
#define E_MAX   1600000

// ------------------------- scratch (device globals) -------------------------
__device__ float g_bufA[N_NODES * HID];          // GEMM outputs (pre-agg)
__device__ float g_bufB[N_NODES * HID];          // z (fp32, post-agg2)
__device__ __half g_qkvh[N_NODES * QK_N];        // Q(256) K(256) per node, fp16
__device__ float g_qkself[N_NODES * 4];
__device__ float g_vw[N_NODES * 4];
__device__ float g_dinv[N_NODES];
__device__ int   g_deg [N_NODES];
__device__ int   g_rowptr[N_NODES + 1];
__device__ int   g_cursor[N_NODES];
__device__ int   g_colsrc[E_MAX];

__device__ __nv_bfloat16 g_xh[N_NODES * IN_CH];
__device__ __nv_bfloat16 g_xl[N_NODES * IN_CH];
__device__ __nv_bfloat16 g_ah[N_NODES * HID];
__device__ __nv_bfloat16 g_al[N_NODES * HID];

__device__ __nv_bfloat16 g_w1h[HID * IN_CH];     // [N=256][K=128]
__device__ __nv_bfloat16 g_w1l[HID * IN_CH];
__device__ __nv_bfloat16 g_w2h[HID * HID];       // [N=256][K=256]
__device__ __nv_bfloat16 g_w2l[HID * HID];
__device__ __nv_bfloat16 g_wqkh[QK_N * HID];     // [N=512][K=256]
__device__ __nv_bfloat16 g_wqkl[QK_N * HID];
__device__ float g_biasqk[QK_N];
__device__ float g_wv[HID * 4];                  // folded V weights [k][h]
__device__ float g_bvw[4];
__device__ float g_wsum[HID];
__device__ float g_bsum;

// ------------------------- helpers -------------------------
__device__ __forceinline__ uint32_t smem_u32(const void* p) {
    uint32_t a;
    asm("{ .reg .u64 t; cvta.to.shared.u64 t, %1; cvt.u32.u64 %0, t; }" : "=r"(a) : "l"(p));
    return a;
}
__device__ __forceinline__ void ldsm_x4(uint32_t* r, uint32_t addr) {
    asm volatile("ldmatrix.sync.aligned.m8n8.x4.shared.b16 {%0,%1,%2,%3}, [%4];"
        : "=r"(r[0]), "=r"(r[1]), "=r"(r[2]), "=r"(r[3]) : "r"(addr));
}
__device__ __forceinline__ void ldsm_x2(uint32_t* r, uint32_t addr) {
    asm volatile("ldmatrix.sync.aligned.m8n8.x2.shared.b16 {%0,%1}, [%2];"
        : "=r"(r[0]), "=r"(r[1]) : "r"(addr));
}
__device__ __forceinline__ void mma_bf16(float* d, const uint32_t* a, const uint32_t* b) {
    asm volatile("mma.sync.aligned.m16n8k16.row.col.f32.bf16.bf16.f32 "
        "{%0,%1,%2,%3}, {%4,%5,%6,%7}, {%8,%9}, {%0,%1,%2,%3};"
        : "+f"(d[0]), "+f"(d[1]), "+f"(d[2]), "+f"(d[3])
        : "r"(a[0]), "r"(a[1]), "r"(a[2]), "r"(a[3]), "r"(b[0]), "r"(b[1]));
}
__device__ __forceinline__ void cp16(uint32_t dst, const void* src) {
    asm volatile("cp.async.cg.shared.global [%0], [%1], 16;" :: "r"(dst), "l"(src));
}
__device__ __forceinline__ void cp16p(uint32_t dst, const void* src, bool pred) {
    int sz = pred ? 16 : 0;
    asm volatile("cp.async.cg.shared.global [%0], [%1], 16, %2;" :: "r"(dst), "l"(src), "r"(sz));
}
__device__ __forceinline__ void split_bf(float x, __nv_bfloat16& h, __nv_bfloat16& l) {
    h = __float2bfloat16_rn(x);
    l = __float2bfloat16_rn(x - __bfloat162float(h));
}

// ------------------------- weight prep -------------------------
__global__ void k_wsum(const float* __restrict__ opw, const float* __restrict__ opb) {
    int i = threadIdx.x;
    float s = 0.f;
    #pragma unroll 4
    for (int j = 0; j < HID; j++) s += opw[j * HID + i];
    g_wsum[i] = s;
    __shared__ float red[256];
    red[i] = opb[i];
    __syncthreads();
    for (int off = 128; off > 0; off >>= 1) {
        if (i < off) red[i] += red[i + off];
        __syncthreads();
    }
    if (i == 0) g_bsum = red[0];
}

__global__ void k_prep_qk(const float* __restrict__ ipw, const float* __restrict__ ipb) {
    int idx = blockIdx.x * blockDim.x + threadIdx.x;
    if (idx >= QK_N * HID) return;
    split_bf(ipw[idx], g_wqkh[idx], g_wqkl[idx]);
    if (idx < QK_N) g_biasqk[idx] = ipb[idx];
}

__global__ void k_prep_vw(const float* __restrict__ ipw, const float* __restrict__ ipb) {
    int idx = blockIdx.x * blockDim.x + threadIdx.x;
    if (idx >= HID * 4) return;
    int k = idx >> 2, h = idx & 3;
    float s = 0.f;
    #pragma unroll 8
    for (int d = 0; d < 64; d++)
        s += g_wsum[h * 64 + d] * ipw[(size_t)(512 + h * 64 + d) * HID + k];
    g_wv[k * 4 + h] = s;
    if (idx < 4) {
        float b = 0.f;
        for (int d = 0; d < 64; d++)
            b += g_wsum[idx * 64 + d] * ipb[512 + idx * 64 + d];
        g_bvw[idx] = b;
    }
}

__global__ void k_prep_w1(const float* __restrict__ W1) {
    int idx = blockIdx.x * blockDim.x + threadIdx.x;   // 256*128
    if (idx >= HID * IN_CH) return;
    int n = idx / IN_CH, k = idx % IN_CH;
    split_bf(W1[k * HID + n], g_w1h[idx], g_w1l[idx]);
}
__global__ void k_prep_w2(const float* __restrict__ W2) {
    int idx = blockIdx.x * blockDim.x + threadIdx.x;   // 256*256
    if (idx >= HID * HID) return;
    int n = idx / HID, k = idx % HID;
    split_bf(W2[k * HID + n], g_w2h[idx], g_w2l[idx]);
}
__global__ void k_cvt_x(const float* __restrict__ x) {
    int idx = blockIdx.x * blockDim.x + threadIdx.x;
    if (idx >= N_NODES * IN_CH) return;
    split_bf(x[idx], g_xh[idx], g_xl[idx]);
}

// ------------------------- degree / CSR build -------------------------
__global__ void k_zero_deg() {
    int i = blockIdx.x * blockDim.x + threadIdx.x;
    if (i < N_NODES) g_deg[i] = 0;
}
__global__ void k_count(const int* __restrict__ ei, int E1) {
    int e = blockIdx.x * blockDim.x + threadIdx.x;
    if (e >= E1) return;
    atomicAdd(&g_deg[ei[E1 + e]], 1);
}
__global__ void k_dinv() {
    int i = blockIdx.x * blockDim.x + threadIdx.x;
    if (i < N_NODES) g_dinv[i] = rsqrtf((float)(g_deg[i] + 1));
}
__global__ void k_scan() {
    __shared__ int sh[1024];
    __shared__ int carry;
    int tid = threadIdx.x;
    if (tid == 0) { carry = 0; g_rowptr[0] = 0; }
    __syncthreads();
    for (int base = 0; base < N_NODES; base += 1024) {
        int i = base + tid;
        int v = (i < N_NODES) ? g_deg[i] : 0;
        sh[tid] = v;
        __syncthreads();
        for (int off = 1; off < 1024; off <<= 1) {
            int t = (tid >= off) ? sh[tid - off] : 0;
            __syncthreads();
            sh[tid] += t;
            __syncthreads();
        }
        if (i < N_NODES) {
            g_cursor[i]     = carry + sh[tid] - v;
            g_rowptr[i + 1] = carry + sh[tid];
        }
        __syncthreads();
        if (tid == 0) carry += sh[1023];
        __syncthreads();
    }
}
__global__ void k_scatter(const int* __restrict__ ei, int E1) {
    int e = blockIdx.x * blockDim.x + threadIdx.x;
    if (e >= E1) return;
    int pos = atomicAdd(&g_cursor[ei[E1 + e]], 1);
    g_colsrc[pos] = ei[e];
}

// ------------------------- split-bf16 GEMM via mma.sync, cp.async double-buffered ---
// C[M,N] = A[M,K] @ Bt[N,K]^T + bias. If Ch != null, write fp16 to Ch instead of C.
#define STR 40                   // padded smem row stride (bf16), 80B rows
#define TILE_B (128 * STR * 2)   // 10240 bytes per tile
#define BUF_B  (4 * TILE_B)      // Ah, Al, Bh, Bl
#define GSM    (2 * BUF_B)       // double buffered: 81920 bytes
__global__ __launch_bounds__(256) void k_gemm_mma(
    const __nv_bfloat16* __restrict__ Ah, const __nv_bfloat16* __restrict__ Al,
    const __nv_bfloat16* __restrict__ Bh, const __nv_bfloat16* __restrict__ Bl,
    const float* __restrict__ bias, float* __restrict__ C, __half* __restrict__ Ch,
    int M, int N, int K, int ldc)
{
    extern __shared__ char smdyn[];
    uint32_t sb = smem_u32(smdyn);

    int tid = threadIdx.x;
    int lane = tid & 31, w = tid >> 5;
    int wm0 = (w >> 2) * 64, wn0 = (w & 3) * 32;
    int m0 = blockIdx.y * 128, n0 = blockIdx.x * 128;

    float acc[4][4][4];
    #pragma unroll
    for (int mt = 0; mt < 4; mt++)
        #pragma unroll
        for (int nt = 0; nt < 4; nt++)
            #pragma unroll
            for (int q = 0; q < 4; q++) acc[mt][nt][q] = 0.f;

    int r8 = lane & 7, sel = lane >> 3;
    uint32_t aoff[4], boff[4];
    #pragma unroll
    for (int mt = 0; mt < 4; mt++)
        aoff[mt] = ((wm0 + mt * 16 + (sel & 1) * 8 + r8) * STR + (sel >> 1) * 8) * 2;
    int selb = sel & 1;
    #pragma unroll
    for (int nt = 0; nt < 4; nt++)
        boff[nt] = ((wn0 + nt * 8 + r8) * STR + selb * 8) * 2;

    int nch = K >> 5;

    // stage chunk `ch` into buffer `buf`
    auto stage = [&](int ch, int buf) {
        int k0 = ch << 5;
        #pragma unroll
        for (int i = 0; i < 2; i++) {
            int lin = tid + i * 256;
            int row = lin >> 2, seg = lin & 3;
            uint32_t dst = sb + buf * BUF_B + row * (STR * 2) + seg * 16;
            int gr = m0 + row;
            bool ok = gr < M;
            int grc = ok ? gr : 0;
            cp16p(dst + 0 * TILE_B, Ah + (size_t)grc * K + k0 + seg * 8, ok);
            cp16p(dst + 1 * TILE_B, Al + (size_t)grc * K + k0 + seg * 8, ok);
            int gn = n0 + row;   // N multiple of 128
            cp16(dst + 2 * TILE_B, Bh + (size_t)gn * K + k0 + seg * 8);
            cp16(dst + 3 * TILE_B, Bl + (size_t)gn * K + k0 + seg * 8);
        }
        asm volatile("cp.async.commit_group;" ::: "memory");
    };

    stage(0, 0);
    for (int ch = 0; ch < nch; ch++) {
        int buf = ch & 1;
        if (ch + 1 < nch) {
            stage(ch + 1, buf ^ 1);
            asm volatile("cp.async.wait_group 1;" ::: "memory");
        } else {
            asm volatile("cp.async.wait_group 0;" ::: "memory");
        }
        __syncthreads();
        uint32_t base = sb + buf * BUF_B;
        #pragma unroll
        for (int ks = 0; ks < 2; ks++) {
            uint32_t ah[4][4], al[4][4], bh[4][2], bl[4][2];
            #pragma unroll
            for (int mt = 0; mt < 4; mt++) {
                ldsm_x4(ah[mt], base + 0 * TILE_B + aoff[mt] + ks * 32);
                ldsm_x4(al[mt], base + 1 * TILE_B + aoff[mt] + ks * 32);
            }
            #pragma unroll
            for (int nt = 0; nt < 4; nt++) {
                ldsm_x2(bh[nt], base + 2 * TILE_B + boff[nt] + ks * 32);
                ldsm_x2(bl[nt], base + 3 * TILE_B + boff[nt] + ks * 32);
            }
            #pragma unroll
            for (int mt = 0; mt < 4; mt++)
                #pragma unroll
                for (int nt = 0; nt < 4; nt++) {
                    mma_bf16(acc[mt][nt], ah[mt], bh[nt]);
                    mma_bf16(acc[mt][nt], al[mt], bh[nt]);
                    mma_bf16(acc[mt][nt], ah[mt], bl[nt]);
                }
        }
        __syncthreads();
    }

    // epilogue
    int g = lane >> 2, tg = lane & 3;
    #pragma unroll
    for (int mt = 0; mt < 4; mt++) {
        #pragma unroll
        for (int nt = 0; nt < 4; nt++) {
            int row = m0 + wm0 + mt * 16 + g;
            int col = n0 + wn0 + nt * 8 + tg * 2;
            float2 bv = *(const float2*)(bias + col);
            float o00 = acc[mt][nt][0] + bv.x, o01 = acc[mt][nt][1] + bv.y;
            float o10 = acc[mt][nt][2] + bv.x, o11 = acc[mt][nt][3] + bv.y;
            if (Ch) {
                if (row < M)
                    *(__half2*)(Ch + (size_t)row * ldc + col) = __floats2half2_rn(o00, o01);
                if (row + 8 < M)
                    *(__half2*)(Ch + (size_t)(row + 8) * ldc + col) = __floats2half2_rn(o10, o11);
            } else {
                if (row < M)
                    *(float2*)(C + (size_t)row * ldc + col) = make_float2(o00, o01);
                if (row + 8 < M)
                    *(float2*)(C + (size_t)(row + 8) * ldc + col) = make_float2(o10, o11);
            }
        }
    }
}

// ------------------------- CSR aggregation (SpMM) -------------------------
__global__ void k_agg(const float* __restrict__ tin, float* __restrict__ outf,
                      __nv_bfloat16* __restrict__ oh, __nv_bfloat16* __restrict__ ol,
                      int relu, int writef) {
    int n = blockIdx.x;
    int t = threadIdx.x;                  // 64 threads x 4 floats
    int beg = g_rowptr[n], end = g_rowptr[n + 1];
    const float4* tv = (const float4*)tin;
    float ax = 0.f, ay = 0.f, az = 0.f, aw = 0.f;
    #pragma unroll 4
    for (int j = beg; j < end; j++) {
        int s = g_colsrc[j];
        float w = g_dinv[s];
        float4 v = tv[(size_t)s * 64 + t];
        ax += w * v.x; ay += w * v.y; az += w * v.z; aw += w * v.w;
    }
    float d = g_dinv[n];
    float d2 = d * d;
    float4 sv = tv[(size_t)n * 64 + t];
    float4 r;
    r.x = d * ax + d2 * sv.x;
    r.y = d * ay + d2 * sv.y;
    r.z = d * az + d2 * sv.z;
    r.w = d * aw + d2 * sv.w;
    if (relu) {
        r.x = fmaxf(r.x, 0.f); r.y = fmaxf(r.y, 0.f);
        r.z = fmaxf(r.z, 0.f); r.w = fmaxf(r.w, 0.f);
    }
    if (writef) ((float4*)outf)[(size_t)n * 64 + t] = r;
    __nv_bfloat16 h0, l0, h1, l1, h2, l2, h3, l3;
    split_bf(r.x, h0, l0); split_bf(r.y, h1, l1);
    split_bf(r.z, h2, l2); split_bf(r.w, h3, l3);
    __nv_bfloat162* ph = (__nv_bfloat162*)oh;
    __nv_bfloat162* pl = (__nv_bfloat162*)ol;
    size_t base = (size_t)n * 128 + t * 2;
    ph[base]     = __nv_bfloat162(h0, h1);
    ph[base + 1] = __nv_bfloat162(h2, h3);
    pl[base]     = __nv_bfloat162(l0, l1);
    pl[base + 1] = __nv_bfloat162(l2, l3);
}

// ------------------------- per-node self scores + folded-V -------------------------
// Q/K fp16: lane owns 8 contiguous dims; head = lane>>3 (8 lanes per 64-dim head).
__global__ void k_qkself() {
    int n = (blockIdx.x * blockDim.x + threadIdx.x) >> 5;
    int lane = threadIdx.x & 31;
    if (n >= N_NODES) return;
    const uint4* qk = (const uint4*)(g_qkvh + (size_t)n * QK_N);
    uint4 qv = qk[lane];        // Q[lane*8 .. +7]
    uint4 kv = qk[32 + lane];   // K[lane*8 .. +7]
    const __half2* qh = (const __half2*)&qv;
    const __half2* kh = (const __half2*)&kv;
    float d = 0.f;
    #pragma unroll
    for (int j = 0; j < 4; j++) {
        float2 a = __half22float2(qh[j]);
        float2 b = __half22float2(kh[j]);
        d += a.x * b.x + a.y * b.y;
    }
    #pragma unroll
    for (int m = 1; m <= 4; m <<= 1) d += __shfl_xor_sync(0xffffffffu, d, m);
    if ((lane & 7) == 0) g_qkself[n * 4 + (lane >> 3)] = d;

    // folded V: vw[h] = z . g_wv[:,h] + bvw[h]  (z fp32)
    const float4* zr = (const float4*)(g_bufB + (size_t)n * HID);
    const float4* wv4 = (const float4*)g_wv;
    float p0 = 0.f, p1 = 0.f, p2 = 0.f, p3 = 0.f;
    #pragma unroll
    for (int half = 0; half < 2; half++) {
        float4 z = zr[lane + half * 32];
        int kb = (lane + half * 32) * 4;
        float4 w0 = wv4[kb], w1 = wv4[kb + 1], w2 = wv4[kb + 2], w3 = wv4[kb + 3];
        p0 += z.x * w0.x + z.y * w1.x + z.z * w2.x + z.w * w3.x;
        p1 += z.x * w0.y + z.y * w1.y + z.z * w2.y + z.w * w3.y;
        p2 += z.x * w0.z + z.y * w1.z + z.z * w2.z + z.w * w3.z;
        p3 += z.x * w0.w + z.y * w1.w + z.z * w2.w + z.w * w3.w;
    }
    #pragma unroll
    for (int m = 16; m > 0; m >>= 1) {
        p0 += __shfl_xor_sync(0xffffffffu, p0, m);
        p1 += __shfl_xor_sync(0xffffffffu, p1, m);
        p2 += __shfl_xor_sync(0xffffffffu, p2, m);
        p3 += __shfl_xor_sync(0xffffffffu, p3, m);
    }
    if (lane == 0) {
        g_vw[n * 4 + 0] = p0 + g_bvw[0];
        g_vw[n * 4 + 1] = p1 + g_bvw[1];
        g_vw[n * 4 + 2] = p2 + g_bvw[2];
        g_vw[n * 4 + 3] = p3 + g_bvw[3];
    }
}

// ------------------------- per-prediction-edge attention -------------------------
__global__ void k_edge(const int* __restrict__ eip, float* __restrict__ out, int E2) {
    int w = (blockIdx.x * blockDim.x + threadIdx.x) >> 5;
    int lane = threadIdx.x & 31;
    if (w >= E2) return;
    int sp = eip[w];
    int dp = eip[E2 + w];
    const uint4* Qr = (const uint4*)(g_qkvh + (size_t)sp * QK_N);
    const uint4* Kr = (const uint4*)(g_qkvh + (size_t)dp * QK_N);
    uint4 qv = Qr[lane];        // Q(sp)[lane*8..]
    uint4 kv = Kr[32 + lane];   // K(dp)[lane*8..]
    const __half2* qh = (const __half2*)&qv;
    const __half2* kh = (const __half2*)&kv;
    float d = 0.f;
    #pragma unroll
    for (int j = 0; j < 4; j++) {
        float2 a = __half22float2(qh[j]);
        float2 b = __half22float2(kh[j]);
        d += a.x * b.x + a.y * b.y;
    }
    #pragma unroll
    for (int m = 1; m <= 4; m <<= 1) d += __shfl_xor_sync(0xffffffffu, d, m);
    float s0 = __shfl_sync(0xffffffffu, d, 0);
    float s1 = __shfl_sync(0xffffffffu, d, 8);
    float s2 = __shfl_sync(0xffffffffu, d, 16);
    float s3 = __shfl_sync(0xffffffffu, d, 24);
    if (lane == 0) {
        float sc[4] = { s0, s1, s2, s3 };     // cross scores q(sp).k(dp)
        const float* vws = g_vw + (size_t)sp * 4;
        const float* vwd = g_vw + (size_t)dp * 4;
        const float* qks = g_qkself + (size_t)sp * 4;
        float acc = g_bsum;
        #pragma unroll
        for (int h = 0; h < 4; h++) {
            float a = 1.f / (1.f + expf((sc[h] - qks[h]) * 0.125f));
            acc += a * vws[h] + (1.f - a) * vwd[h];
        }
        out[w] = 1.f / (1.f + expf(-acc));
    }
}

// ------------------------- launch -------------------------
extern "C" void kernel_launch(void* const* d_in, const int* in_sizes, int n_in,
                              void* d_out, int out_size) {
    const float* x   = (const float*)d_in[0];
    const int* ei    = (const int*)d_in[1];
    const int* eip   = (const int*)d_in[2];
    const float* W1  = (const float*)d_in[3];
    const float* b1  = (const float*)d_in[4];
    const float* W2  = (const float*)d_in[5];
    const float* b2  = (const float*)d_in[6];
    const float* ipw = (const float*)d_in[7];
    const float* ipb = (const float*)d_in[8];
    const float* opw = (const float*)d_in[9];
    const float* opb = (const float*)d_in[10];
    float* out       = (float*)d_out;

    int E1 = in_sizes[1] / 2;
    int E2 = in_sizes[2] / 2;

    static bool attr_set = false;
    if (!attr_set) {
        cudaFuncSetAttribute(k_gemm_mma, cudaFuncAttributeMaxDynamicSharedMemorySize, GSM);
        attr_set = true;
    }

    float *pA, *pB, *pBqk;
    __half* pQKV;
    __nv_bfloat16 *pxh, *pxl, *pah, *pal, *pw1h, *pw1l, *pw2h, *pw2l, *pwqh, *pwql;
    cudaGetSymbolAddress((void**)&pA,   g_bufA);
    cudaGetSymbolAddress((void**)&pB,   g_bufB);
    cudaGetSymbolAddress((void**)&pQKV, g_qkvh);
    cudaGetSymbolAddress((void**)&pBqk, g_biasqk);
    cudaGetSymbolAddress((void**)&pxh,  g_xh);
    cudaGetSymbolAddress((void**)&pxl,  g_xl);
    cudaGetSymbolAddress((void**)&pah,  g_ah);
    cudaGetSymbolAddress((void**)&pal,  g_al);
    cudaGetSymbolAddress((void**)&pw1h, g_w1h);
    cudaGetSymbolAddress((void**)&pw1l, g_w1l);
    cudaGetSymbolAddress((void**)&pw2h, g_w2h);
    cudaGetSymbolAddress((void**)&pw2l, g_w2l);
    cudaGetSymbolAddress((void**)&pwqh, g_wqkh);
    cudaGetSymbolAddress((void**)&pwql, g_wqkl);

    // weight prep + input conversion
    k_wsum<<<1, 256>>>(opw, opb);
    k_prep_qk<<<(QK_N * HID + 255) / 256, 256>>>(ipw, ipb);
    k_prep_vw<<<4, 256>>>(ipw, ipb);
    k_prep_w1<<<(HID * IN_CH + 255) / 256, 256>>>(W1);
    k_prep_w2<<<(HID * HID + 255) / 256, 256>>>(W2);
    k_cvt_x<<<(N_NODES * IN_CH + 255) / 256, 256>>>(x);

    // degree + CSR
    k_zero_deg<<<(N_NODES + 255) / 256, 256>>>();
    k_count<<<(E1 + 255) / 256, 256>>>(ei, E1);
    k_dinv<<<(N_NODES + 255) / 256, 256>>>();
    k_scan<<<1, 1024>>>();
    k_scatter<<<(E1 + 255) / 256, 256>>>(ei, E1);

    dim3 g1(HID / 128, (N_NODES + 127) / 128);
    dim3 g3(QK_N / 128, (N_NODES + 127) / 128);

    // GCN layer 1: h = relu(agg(x@W1+b1))
    k_gemm_mma<<<g1, 256, GSM>>>(pxh, pxl, pw1h, pw1l, b1, pA, nullptr,
                                 N_NODES, HID, IN_CH, HID);
    k_agg<<<N_NODES, 64>>>(pA, nullptr, pah, pal, 1, 0);

    // GCN layer 2: z = agg(h@W2+b2)
    k_gemm_mma<<<g1, 256, GSM>>>(pah, pal, pw2h, pw2l, b2, pA, nullptr,
                                 N_NODES, HID, HID, HID);
    k_agg<<<N_NODES, 64>>>(pA, pB, pah, pal, 0, 1);

    // QK projection (512 cols) -> fp16 output
    k_gemm_mma<<<g3, 256, GSM>>>(pah, pal, pwqh, pwql, pBqk, nullptr, pQKV,
                                 N_NODES, QK_N, HID, QK_N);

    // self scores + folded V, then per-edge attention
    k_qkself<<<(N_NODES * 32 + 255) / 256, 256>>>();
    k_edge<<<((size_t)E2 * 32 + 255) / 256, 256>>>(eip, out, E2);
}

// round 6
// speedup vs baseline: 2.3451x; 1.2867x over previous
#include <cuda_runtime.h>
#include <cuda_bf16.h>
#include <cuda_fp16.h>
#include <math.h>
#include <stdint.h>

#define N_NODES 50000
#define IN_CH   128
#define HID     256
#define QK_N    512
#define E_MAX   1600000

// ------------------------- scratch (device globals) -------------------------
__device__ __half g_t16[N_NODES * HID];          // GEMM1/2 outputs (pre-agg), fp16
__device__ __half g_z16[N_NODES * HID];          // z post-agg2, fp16
__device__ __half g_qkvh[N_NODES * QK_N];        // Q(256) K(256) per node, fp16
__device__ float g_qkself[N_NODES * 4];
__device__ float g_vw[N_NODES * 4];
__device__ float g_dinv[N_NODES];
__device__ int   g_deg [N_NODES];
__device__ int   g_rowptr[N_NODES + 1];
__device__ int   g_cursor[N_NODES];
__device__ int   g_colsrc[E_MAX];
__device__ int   g_bsums[64];
__device__ int   g_boff[64];

__device__ __nv_bfloat16 g_xh[N_NODES * IN_CH];
__device__ __nv_bfloat16 g_xl[N_NODES * IN_CH];
__device__ __nv_bfloat16 g_ah[N_NODES * HID];
__device__ __nv_bfloat16 g_al[N_NODES * HID];

__device__ __nv_bfloat16 g_w1h[HID * IN_CH];     // [N=256][K=128]
__device__ __nv_bfloat16 g_w1l[HID * IN_CH];
__device__ __nv_bfloat16 g_w2h[HID * HID];       // [N=256][K=256]
__device__ __nv_bfloat16 g_w2l[HID * HID];
__device__ __half g_wqk16[QK_N * HID];           // [N=512][K=256] fp16
__device__ float g_biasqk[QK_N];
__device__ float g_wv[HID * 4];                  // folded V weights [k][h]
__device__ float g_bvw[4];
__device__ float g_wsum[HID];
__device__ float g_bsum;

// ------------------------- helpers -------------------------
__device__ __forceinline__ uint32_t smem_u32(const void* p) {
    uint32_t a;
    asm("{ .reg .u64 t; cvta.to.shared.u64 t, %1; cvt.u32.u64 %0, t; }" : "=r"(a) : "l"(p));
    return a;
}
__device__ __forceinline__ void ldsm_x4(uint32_t* r, uint32_t addr) {
    asm volatile("ldmatrix.sync.aligned.m8n8.x4.shared.b16 {%0,%1,%2,%3}, [%4];"
        : "=r"(r[0]), "=r"(r[1]), "=r"(r[2]), "=r"(r[3]) : "r"(addr));
}
__device__ __forceinline__ void ldsm_x2(uint32_t* r, uint32_t addr) {
    asm volatile("ldmatrix.sync.aligned.m8n8.x2.shared.b16 {%0,%1}, [%2];"
        : "=r"(r[0]), "=r"(r[1]) : "r"(addr));
}
__device__ __forceinline__ void mma_bf16(float* d, const uint32_t* a, const uint32_t* b) {
    asm volatile("mma.sync.aligned.m16n8k16.row.col.f32.bf16.bf16.f32 "
        "{%0,%1,%2,%3}, {%4,%5,%6,%7}, {%8,%9}, {%0,%1,%2,%3};"
        : "+f"(d[0]), "+f"(d[1]), "+f"(d[2]), "+f"(d[3])
        : "r"(a[0]), "r"(a[1]), "r"(a[2]), "r"(a[3]), "r"(b[0]), "r"(b[1]));
}
__device__ __forceinline__ void mma_f16(float* d, const uint32_t* a, const uint32_t* b) {
    asm volatile("mma.sync.aligned.m16n8k16.row.col.f32.f16.f16.f32 "
        "{%0,%1,%2,%3}, {%4,%5,%6,%7}, {%8,%9}, {%0,%1,%2,%3};"
        : "+f"(d[0]), "+f"(d[1]), "+f"(d[2]), "+f"(d[3])
        : "r"(a[0]), "r"(a[1]), "r"(a[2]), "r"(a[3]), "r"(b[0]), "r"(b[1]));
}
__device__ __forceinline__ void cp16(uint32_t dst, const void* src) {
    asm volatile("cp.async.cg.shared.global [%0], [%1], 16;" :: "r"(dst), "l"(src));
}
__device__ __forceinline__ void cp16p(uint32_t dst, const void* src, bool pred) {
    int sz = pred ? 16 : 0;
    asm volatile("cp.async.cg.shared.global [%0], [%1], 16, %2;" :: "r"(dst), "l"(src), "r"(sz));
}
__device__ __forceinline__ void split_bf(float x, __nv_bfloat16& h, __nv_bfloat16& l) {
    h = __float2bfloat16_rn(x);
    l = __float2bfloat16_rn(x - __bfloat162float(h));
}

// ------------------------- weight prep -------------------------
__global__ void k_wsum(const float* __restrict__ opw, const float* __restrict__ opb) {
    int i = threadIdx.x;
    float s = 0.f;
    #pragma unroll 4
    for (int j = 0; j < HID; j++) s += opw[j * HID + i];
    g_wsum[i] = s;
    __shared__ float red[256];
    red[i] = opb[i];
    __syncthreads();
    for (int off = 128; off > 0; off >>= 1) {
        if (i < off) red[i] += red[i + off];
        __syncthreads();
    }
    if (i == 0) g_bsum = red[0];
}

// merged weight conversion: W1 split, W2 split, Wqk fp16 (+bias)
__global__ void k_prep_w(const float* __restrict__ W1, const float* __restrict__ W2,
                         const float* __restrict__ ipw, const float* __restrict__ ipb) {
    int idx = blockIdx.x * blockDim.x + threadIdx.x;
    if (idx < 32768) {
        int n = idx >> 7, k = idx & 127;
        split_bf(W1[k * HID + n], g_w1h[idx], g_w1l[idx]);
    } else if (idx < 98304) {
        int j = idx - 32768;
        int n = j >> 8, k = j & 255;
        split_bf(W2[k * HID + n], g_w2h[j], g_w2l[j]);
    } else if (idx < 229376) {
        int j = idx - 98304;
        g_wqk16[j] = __float2half(ipw[j]);
        if (j < QK_N) g_biasqk[j] = ipb[j];
    }
}

__global__ void k_prep_vw(const float* __restrict__ ipw, const float* __restrict__ ipb) {
    int idx = blockIdx.x * blockDim.x + threadIdx.x;
    if (idx >= HID * 4) return;
    int k = idx >> 2, h = idx & 3;
    float s = 0.f;
    #pragma unroll 8
    for (int d = 0; d < 64; d++)
        s += g_wsum[h * 64 + d] * ipw[(size_t)(512 + h * 64 + d) * HID + k];
    g_wv[k * 4 + h] = s;
    if (idx < 4) {
        float b = 0.f;
        for (int d = 0; d < 64; d++)
            b += g_wsum[idx * 64 + d] * ipb[512 + idx * 64 + d];
        g_bvw[idx] = b;
    }
}

__global__ void k_cvt_x(const float* __restrict__ x) {
    int idx = blockIdx.x * blockDim.x + threadIdx.x;
    if (idx >= N_NODES * IN_CH) return;
    split_bf(x[idx], g_xh[idx], g_xl[idx]);
}

// ------------------------- degree / CSR build -------------------------
__global__ void k_zero_deg() {
    int i = blockIdx.x * blockDim.x + threadIdx.x;
    if (i < N_NODES) g_deg[i] = 0;
}
__global__ void k_count(const int* __restrict__ ei, int E1) {
    int e = blockIdx.x * blockDim.x + threadIdx.x;
    if (e >= E1) return;
    atomicAdd(&g_deg[ei[E1 + e]], 1);
}
__global__ void k_dinv() {
    int i = blockIdx.x * blockDim.x + threadIdx.x;
    if (i < N_NODES) g_dinv[i] = rsqrtf((float)(g_deg[i] + 1));
}
// 3-phase parallel exclusive scan of deg -> rowptr/cursor
__global__ void k_scanA() {
    int b = blockIdx.x, t = threadIdx.x;
    int i = b * 1024 + t;
    int v = (i < N_NODES) ? g_deg[i] : 0;
    int lane = t & 31, w = t >> 5;
    int x = v;
    #pragma unroll
    for (int o = 1; o < 32; o <<= 1) {
        int y = __shfl_up_sync(0xffffffffu, x, o);
        if (lane >= o) x += y;
    }
    __shared__ int ws[32];
    if (lane == 31) ws[w] = x;
    __syncthreads();
    if (w == 0) {
        int s = ws[lane];
        #pragma unroll
        for (int o = 1; o < 32; o <<= 1) {
            int y = __shfl_up_sync(0xffffffffu, s, o);
            if (lane >= o) s += y;
        }
        ws[lane] = s;
    }
    __syncthreads();
    int incl = x + (w > 0 ? ws[w - 1] : 0);
    if (i < N_NODES) g_cursor[i] = incl;   // temp: local inclusive scan
    if (t == 1023) g_bsums[b] = incl;
}
__global__ void k_scanB(int nblk) {
    __shared__ int sh[64];
    int t = threadIdx.x;
    int v = (t < nblk) ? g_bsums[t] : 0;
    sh[t] = v;
    __syncthreads();
    for (int o = 1; o < 64; o <<= 1) {
        int y = (t >= o) ? sh[t - o] : 0;
        __syncthreads();
        sh[t] += y;
        __syncthreads();
    }
    g_boff[t] = sh[t] - v;   // exclusive block offset
}
__global__ void k_scanC() {
    int b = blockIdx.x, t = threadIdx.x;
    int i = b * 1024 + t;
    if (i < N_NODES) {
        int inc = g_cursor[i] + g_boff[b];
        g_rowptr[i + 1] = inc;
        g_cursor[i] = inc - g_deg[i];
    }
    if (i == 0) g_rowptr[0] = 0;
}
__global__ void k_scatter(const int* __restrict__ ei, int E1) {
    int e = blockIdx.x * blockDim.x + threadIdx.x;
    if (e >= E1) return;
    int pos = atomicAdd(&g_cursor[ei[E1 + e]], 1);
    g_colsrc[pos] = ei[e];
}

// ------------------------- GEMM via mma.sync, cp.async double-buffered -------------
// TERMS==3: split-bf16 (Ah*Bh + Al*Bh + Ah*Bl), operands bf16 hi/lo.
// TERMS==1: plain fp16 (A0*B0), operands fp16.
// Output always fp16 (+fp32 bias).
#define STR 40                   // padded smem row stride (16-bit elems), 80B rows
#define TILE_B (128 * STR * 2)   // 10240 bytes per tile
template <int TERMS>
__global__ __launch_bounds__(256) void k_gemm(
    const void* __restrict__ A0, const void* __restrict__ A1,
    const void* __restrict__ B0, const void* __restrict__ B1,
    const float* __restrict__ bias, __half* __restrict__ Ch,
    int M, int N, int K, int ldc)
{
    constexpr int NT   = (TERMS == 3) ? 4 : 2;
    constexpr int BUFB = NT * TILE_B;
    constexpr uint32_t OFF_A0 = 0;
    constexpr uint32_t OFF_A1 = TILE_B;                       // TERMS==3 only
    constexpr uint32_t OFF_B0 = (TERMS == 3) ? 2 * TILE_B : TILE_B;
    constexpr uint32_t OFF_B1 = 3 * TILE_B;                   // TERMS==3 only

    extern __shared__ char smdyn[];
    uint32_t sb = smem_u32(smdyn);

    int tid = threadIdx.x;
    int lane = tid & 31, w = tid >> 5;
    int wm0 = (w >> 2) * 64, wn0 = (w & 3) * 32;
    int m0 = blockIdx.y * 128, n0 = blockIdx.x * 128;

    float acc[4][4][4];
    #pragma unroll
    for (int mt = 0; mt < 4; mt++)
        #pragma unroll
        for (int nt = 0; nt < 4; nt++)
            #pragma unroll
            for (int q = 0; q < 4; q++) acc[mt][nt][q] = 0.f;

    int r8 = lane & 7, sel = lane >> 3;
    uint32_t aoff[4], boff[4];
    #pragma unroll
    for (int mt = 0; mt < 4; mt++)
        aoff[mt] = ((wm0 + mt * 16 + (sel & 1) * 8 + r8) * STR + (sel >> 1) * 8) * 2;
    int selb = sel & 1;
    #pragma unroll
    for (int nt = 0; nt < 4; nt++)
        boff[nt] = ((wn0 + nt * 8 + r8) * STR + selb * 8) * 2;

    int nch = K >> 5;

    auto stage = [&](int ch, int buf) {
        int k0 = ch << 5;
        #pragma unroll
        for (int i = 0; i < 2; i++) {
            int lin = tid + i * 256;
            int row = lin >> 2, seg = lin & 3;
            uint32_t dst = sb + buf * BUFB + row * (STR * 2) + seg * 16;
            int gr = m0 + row;
            bool ok = gr < M;
            int grc = ok ? gr : 0;
            int gn = n0 + row;   // N multiple of 128
            if (TERMS == 3) {
                cp16p(dst + OFF_A0, (const __nv_bfloat16*)A0 + (size_t)grc * K + k0 + seg * 8, ok);
                cp16p(dst + OFF_A1, (const __nv_bfloat16*)A1 + (size_t)grc * K + k0 + seg * 8, ok);
                cp16(dst + OFF_B0, (const __nv_bfloat16*)B0 + (size_t)gn * K + k0 + seg * 8);
                cp16(dst + OFF_B1, (const __nv_bfloat16*)B1 + (size_t)gn * K + k0 + seg * 8);
            } else {
                cp16p(dst + OFF_A0, (const __half*)A0 + (size_t)grc * K + k0 + seg * 8, ok);
                cp16(dst + OFF_B0, (const __half*)B0 + (size_t)gn * K + k0 + seg * 8);
            }
        }
        asm volatile("cp.async.commit_group;" ::: "memory");
    };

    stage(0, 0);
    for (int ch = 0; ch < nch; ch++) {
        int buf = ch & 1;
        if (ch + 1 < nch) {
            stage(ch + 1, buf ^ 1);
            asm volatile("cp.async.wait_group 1;" ::: "memory");
        } else {
            asm volatile("cp.async.wait_group 0;" ::: "memory");
        }
        __syncthreads();
        uint32_t base = sb + buf * BUFB;
        #pragma unroll
        for (int ks = 0; ks < 2; ks++) {
            uint32_t ah[4][4], al[4][4], bh[4][2], bl[4][2];
            #pragma unroll
            for (int mt = 0; mt < 4; mt++) {
                ldsm_x4(ah[mt], base + OFF_A0 + aoff[mt] + ks * 32);
                if (TERMS == 3) ldsm_x4(al[mt], base + OFF_A1 + aoff[mt] + ks * 32);
            }
            #pragma unroll
            for (int nt = 0; nt < 4; nt++) {
                ldsm_x2(bh[nt], base + OFF_B0 + boff[nt] + ks * 32);
                if (TERMS == 3) ldsm_x2(bl[nt], base + OFF_B1 + boff[nt] + ks * 32);
            }
            #pragma unroll
            for (int mt = 0; mt < 4; mt++)
                #pragma unroll
                for (int nt = 0; nt < 4; nt++) {
                    if (TERMS == 3) {
                        mma_bf16(acc[mt][nt], ah[mt], bh[nt]);
                        mma_bf16(acc[mt][nt], al[mt], bh[nt]);
                        mma_bf16(acc[mt][nt], ah[mt], bl[nt]);
                    } else {
                        mma_f16(acc[mt][nt], ah[mt], bh[nt]);
                    }
                }
        }
        __syncthreads();
    }

    // epilogue: fp32 bias, fp16 stores
    int g = lane >> 2, tg = lane & 3;
    #pragma unroll
    for (int mt = 0; mt < 4; mt++) {
        #pragma unroll
        for (int nt = 0; nt < 4; nt++) {
            int row = m0 + wm0 + mt * 16 + g;
            int col = n0 + wn0 + nt * 8 + tg * 2;
            float2 bv = *(const float2*)(bias + col);
            if (row < M)
                *(__half2*)(Ch + (size_t)row * ldc + col) =
                    __floats2half2_rn(acc[mt][nt][0] + bv.x, acc[mt][nt][1] + bv.y);
            if (row + 8 < M)
                *(__half2*)(Ch + (size_t)(row + 8) * ldc + col) =
                    __floats2half2_rn(acc[mt][nt][2] + bv.x, acc[mt][nt][3] + bv.y);
        }
    }
}
#define GSM3 (2 * 4 * TILE_B)
#define GSM1 (2 * 2 * TILE_B)

// ------------------------- CSR aggregation (fp16 gathers) -------------------------
// agg1: out = relu(D^-1/2 (A+I) D^-1/2 t), writes bf16 hi/lo for GEMM2
__global__ void k_agg1(const __half* __restrict__ tin) {
    int n = blockIdx.x;
    int t = threadIdx.x;                  // 64 threads, each owns 4 channels
    int beg = g_rowptr[n], end = g_rowptr[n + 1];
    const uint2* tv = (const uint2*)tin;  // row = 64 uint2 (512B)
    float a0 = 0.f, a1 = 0.f, a2 = 0.f, a3 = 0.f;
    #pragma unroll 4
    for (int j = beg; j < end; j++) {
        int s = g_colsrc[j];
        float w = g_dinv[s];
        uint2 v = tv[(size_t)s * 64 + t];
        float2 f01 = __half22float2(*(const __half2*)&v.x);
        float2 f23 = __half22float2(*(const __half2*)&v.y);
        a0 += w * f01.x; a1 += w * f01.y; a2 += w * f23.x; a3 += w * f23.y;
    }
    float d = g_dinv[n], d2 = d * d;
    uint2 sv = tv[(size_t)n * 64 + t];
    float2 s01 = __half22float2(*(const __half2*)&sv.x);
    float2 s23 = __half22float2(*(const __half2*)&sv.y);
    float r0 = fmaxf(d * a0 + d2 * s01.x, 0.f);
    float r1 = fmaxf(d * a1 + d2 * s01.y, 0.f);
    float r2 = fmaxf(d * a2 + d2 * s23.x, 0.f);
    float r3 = fmaxf(d * a3 + d2 * s23.y, 0.f);
    __nv_bfloat16 h0, l0, h1, l1, h2, l2, h3, l3;
    split_bf(r0, h0, l0); split_bf(r1, h1, l1);
    split_bf(r2, h2, l2); split_bf(r3, h3, l3);
    __nv_bfloat162* ph = (__nv_bfloat162*)g_ah;
    __nv_bfloat162* pl = (__nv_bfloat162*)g_al;
    size_t base = (size_t)n * 128 + t * 2;
    ph[base]     = __nv_bfloat162(h0, h1);
    ph[base + 1] = __nv_bfloat162(h2, h3);
    pl[base]     = __nv_bfloat162(l0, l1);
    pl[base + 1] = __nv_bfloat162(l2, l3);
}

// agg2: z = D^-1/2 (A+I) D^-1/2 t; writes fp16 z + fused folded-V (vw = z.wv + bvw)
__global__ void k_agg2(const __half* __restrict__ tin) {
    int n = blockIdx.x;
    int t = threadIdx.x;
    int lane = t & 31, wrp = t >> 5;
    int beg = g_rowptr[n], end = g_rowptr[n + 1];
    const uint2* tv = (const uint2*)tin;
    float a0 = 0.f, a1 = 0.f, a2 = 0.f, a3 = 0.f;
    #pragma unroll 4
    for (int j = beg; j < end; j++) {
        int s = g_colsrc[j];
        float w = g_dinv[s];
        uint2 v = tv[(size_t)s * 64 + t];
        float2 f01 = __half22float2(*(const __half2*)&v.x);
        float2 f23 = __half22float2(*(const __half2*)&v.y);
        a0 += w * f01.x; a1 += w * f01.y; a2 += w * f23.x; a3 += w * f23.y;
    }
    float d = g_dinv[n], d2 = d * d;
    uint2 sv = tv[(size_t)n * 64 + t];
    float2 s01 = __half22float2(*(const __half2*)&sv.x);
    float2 s23 = __half22float2(*(const __half2*)&sv.y);
    float r0 = d * a0 + d2 * s01.x;
    float r1 = d * a1 + d2 * s01.y;
    float r2 = d * a2 + d2 * s23.x;
    float r3 = d * a3 + d2 * s23.y;
    // z fp16
    uint2 zo;
    *(__half2*)&zo.x = __floats2half2_rn(r0, r1);
    *(__half2*)&zo.y = __floats2half2_rn(r2, r3);
    ((uint2*)g_z16)[(size_t)n * 64 + t] = zo;
    // folded V partials: channels t*4..t*4+3
    const float4* wv4 = (const float4*)g_wv;
    float4 w0 = wv4[t * 4], w1 = wv4[t * 4 + 1], w2 = wv4[t * 4 + 2], w3 = wv4[t * 4 + 3];
    float p0 = r0 * w0.x + r1 * w1.x + r2 * w2.x + r3 * w3.x;
    float p1 = r0 * w0.y + r1 * w1.y + r2 * w2.y + r3 * w3.y;
    float p2 = r0 * w0.z + r1 * w1.z + r2 * w2.z + r3 * w3.z;
    float p3 = r0 * w0.w + r1 * w1.w + r2 * w2.w + r3 * w3.w;
    #pragma unroll
    for (int m = 16; m > 0; m >>= 1) {
        p0 += __shfl_xor_sync(0xffffffffu, p0, m);
        p1 += __shfl_xor_sync(0xffffffffu, p1, m);
        p2 += __shfl_xor_sync(0xffffffffu, p2, m);
        p3 += __shfl_xor_sync(0xffffffffu, p3, m);
    }
    __shared__ float sp[2][4];
    if (lane == 0) {
        sp[wrp][0] = p0; sp[wrp][1] = p1; sp[wrp][2] = p2; sp[wrp][3] = p3;
    }
    __syncthreads();
    if (t < 4)
        g_vw[n * 4 + t] = sp[0][t] + sp[1][t] + g_bvw[t];
}

// ------------------------- per-node self scores -------------------------
__global__ void k_qkself() {
    int n = (blockIdx.x * blockDim.x + threadIdx.x) >> 5;
    int lane = threadIdx.x & 31;
    if (n >= N_NODES) return;
    const uint4* qk = (const uint4*)(g_qkvh + (size_t)n * QK_N);
    uint4 qv = qk[lane];        // Q[lane*8 .. +7]
    uint4 kv = qk[32 + lane];   // K[lane*8 .. +7]
    const __half2* qh = (const __half2*)&qv;
    const __half2* kh = (const __half2*)&kv;
    float d = 0.f;
    #pragma unroll
    for (int j = 0; j < 4; j++) {
        float2 a = __half22float2(qh[j]);
        float2 b = __half22float2(kh[j]);
        d += a.x * b.x + a.y * b.y;
    }
    #pragma unroll
    for (int m = 1; m <= 4; m <<= 1) d += __shfl_xor_sync(0xffffffffu, d, m);
    if ((lane & 7) == 0) g_qkself[n * 4 + (lane >> 3)] = d;
}

// ------------------------- per-prediction-edge attention -------------------------
__global__ void k_edge(const int* __restrict__ eip, float* __restrict__ out, int E2) {
    int w = (blockIdx.x * blockDim.x + threadIdx.x) >> 5;
    int lane = threadIdx.x & 31;
    if (w >= E2) return;
    int sp = eip[w];
    int dp = eip[E2 + w];
    const uint4* Qr = (const uint4*)(g_qkvh + (size_t)sp * QK_N);
    const uint4* Kr = (const uint4*)(g_qkvh + (size_t)dp * QK_N);
    uint4 qv = Qr[lane];        // Q(sp)[lane*8..]
    uint4 kv = Kr[32 + lane];   // K(dp)[lane*8..]
    const __half2* qh = (const __half2*)&qv;
    const __half2* kh = (const __half2*)&kv;
    float d = 0.f;
    #pragma unroll
    for (int j = 0; j < 4; j++) {
        float2 a = __half22float2(qh[j]);
        float2 b = __half22float2(kh[j]);
        d += a.x * b.x + a.y * b.y;
    }
    #pragma unroll
    for (int m = 1; m <= 4; m <<= 1) d += __shfl_xor_sync(0xffffffffu, d, m);
    float s0 = __shfl_sync(0xffffffffu, d, 0);
    float s1 = __shfl_sync(0xffffffffu, d, 8);
    float s2 = __shfl_sync(0xffffffffu, d, 16);
    float s3 = __shfl_sync(0xffffffffu, d, 24);
    if (lane == 0) {
        float sc[4] = { s0, s1, s2, s3 };     // cross scores q(sp).k(dp)
        const float* vws = g_vw + (size_t)sp * 4;
        const float* vwd = g_vw + (size_t)dp * 4;
        const float* qks = g_qkself + (size_t)sp * 4;
        float acc = g_bsum;
        #pragma unroll
        for (int h = 0; h < 4; h++) {
            float a = 1.f / (1.f + expf((sc[h] - qks[h]) * 0.125f));
            acc += a * vws[h] + (1.f - a) * vwd[h];
        }
        out[w] = 1.f / (1.f + expf(-acc));
    }
}

// ------------------------- launch -------------------------
extern "C" void kernel_launch(void* const* d_in, const int* in_sizes, int n_in,
                              void* d_out, int out_size) {
    const float* x   = (const float*)d_in[0];
    const int* ei    = (const int*)d_in[1];
    const int* eip   = (const int*)d_in[2];
    const float* W1  = (const float*)d_in[3];
    const float* b1  = (const float*)d_in[4];
    const float* W2  = (const float*)d_in[5];
    const float* b2  = (const float*)d_in[6];
    const float* ipw = (const float*)d_in[7];
    const float* ipb = (const float*)d_in[8];
    const float* opw = (const float*)d_in[9];
    const float* opb = (const float*)d_in[10];
    float* out       = (float*)d_out;

    int E1 = in_sizes[1] / 2;
    int E2 = in_sizes[2] / 2;

    static bool attr_set = false;
    if (!attr_set) {
        cudaFuncSetAttribute(k_gemm<3>, cudaFuncAttributeMaxDynamicSharedMemorySize, GSM3);
        cudaFuncSetAttribute(k_gemm<1>, cudaFuncAttributeMaxDynamicSharedMemorySize, GSM1);
        attr_set = true;
    }

    float* pBqk;
    __half *pT, *pZ, *pQKV, *pWqk;
    __nv_bfloat16 *pxh, *pxl, *pah, *pal, *pw1h, *pw1l, *pw2h, *pw2l;
    cudaGetSymbolAddress((void**)&pT,   g_t16);
    cudaGetSymbolAddress((void**)&pZ,   g_z16);
    cudaGetSymbolAddress((void**)&pQKV, g_qkvh);
    cudaGetSymbolAddress((void**)&pWqk, g_wqk16);
    cudaGetSymbolAddress((void**)&pBqk, g_biasqk);
    cudaGetSymbolAddress((void**)&pxh,  g_xh);
    cudaGetSymbolAddress((void**)&pxl,  g_xl);
    cudaGetSymbolAddress((void**)&pah,  g_ah);
    cudaGetSymbolAddress((void**)&pal,  g_al);
    cudaGetSymbolAddress((void**)&pw1h, g_w1h);
    cudaGetSymbolAddress((void**)&pw1l, g_w1l);
    cudaGetSymbolAddress((void**)&pw2h, g_w2h);
    cudaGetSymbolAddress((void**)&pw2l, g_w2l);

    // weight prep + input conversion
    k_wsum<<<1, 256>>>(opw, opb);
    k_prep_w<<<896, 256>>>(W1, W2, ipw, ipb);
    k_prep_vw<<<4, 256>>>(ipw, ipb);
    k_cvt_x<<<(N_NODES * IN_CH + 255) / 256, 256>>>(x);

    // degree + CSR (parallel scan)
    k_zero_deg<<<(N_NODES + 255) / 256, 256>>>();
    k_count<<<(E1 + 255) / 256, 256>>>(ei, E1);
    k_dinv<<<(N_NODES + 255) / 256, 256>>>();
    int nblk = (N_NODES + 1023) / 1024;
    k_scanA<<<nblk, 1024>>>();
    k_scanB<<<1, 64>>>(nblk);
    k_scanC<<<nblk, 1024>>>();
    k_scatter<<<(E1 + 255) / 256, 256>>>(ei, E1);

    dim3 g1(HID / 128, (N_NODES + 127) / 128);
    dim3 g3(QK_N / 128, (N_NODES + 127) / 128);

    // GCN layer 1: t1 = x@W1+b1 (split-bf16), h = relu(agg(t1))
    k_gemm<3><<<g1, 256, GSM3>>>(pxh, pxl, pw1h, pw1l, b1, pT,
                                 N_NODES, HID, IN_CH, HID);
    k_agg1<<<N_NODES, 64>>>(pT);

    // GCN layer 2: t2 = h@W2+b2 (split-bf16), z = agg(t2) + fused vw
    k_gemm<3><<<g1, 256, GSM3>>>(pah, pal, pw2h, pw2l, b2, pT,
                                 N_NODES, HID, HID, HID);
    k_agg2<<<N_NODES, 64>>>(pT);

    // QK projection (512 cols), plain fp16
    k_gemm<1><<<g3, 256, GSM1>>>(pZ, nullptr, pWqk, nullptr, pBqk, pQKV,
                                 N_NODES, QK_N, HID, QK_N);

    // self scores, then per-edge attention
    k_qkself<<<(N_NODES * 32 + 255) / 256, 256>>>();
    k_edge<<<((size_t)E2 * 32 + 255) / 256, 256>>>(eip, out, E2);
}

// round 7
// speedup vs baseline: 2.6202x; 1.1173x over previous
#include <cuda_runtime.h>
#include <cuda_fp16.h>
#include <math.h>
#include <stdint.h>

#define N_NODES 50000
#define IN_CH   128
#define HID     256
#define QK_N    512
#define E_MAX   1600000

// ------------------------- scratch (device globals) -------------------------
__device__ __half g_x16[N_NODES * IN_CH];        // x, fp16
__device__ __half g_t16[N_NODES * HID];          // GEMM1/2 outputs (pre-agg), fp16
__device__ __half g_h16[N_NODES * HID];          // h post-agg1, fp16
__device__ __half g_z16[N_NODES * HID];          // z post-agg2, fp16
__device__ __half g_qkvh[N_NODES * QK_N];        // Q(256) K(256) per node, fp16
__device__ float g_qkself[N_NODES * 4];
__device__ float g_vw[N_NODES * 4];
__device__ float g_dinv[N_NODES];
__device__ int   g_deg [N_NODES];
__device__ int   g_rowptr[N_NODES + 1];
__device__ int   g_cursor[N_NODES];
__device__ int   g_colsrc[E_MAX];
__device__ int   g_bsums[64];
__device__ int   g_boff[64];

__device__ __half g_w1[HID * IN_CH];             // [N=256][K=128] fp16
__device__ __half g_w2[HID * HID];               // [N=256][K=256] fp16
__device__ __half g_wqk[QK_N * HID];             // [N=512][K=256] fp16
__device__ float g_biasqk[QK_N];
__device__ float g_wv[HID * 4];                  // folded V weights [k][h]
__device__ float g_bvw[4];
__device__ float g_wsum[HID];
__device__ float g_bsum;

// ------------------------- helpers -------------------------
__device__ __forceinline__ uint32_t smem_u32(const void* p) {
    uint32_t a;
    asm("{ .reg .u64 t; cvta.to.shared.u64 t, %1; cvt.u32.u64 %0, t; }" : "=r"(a) : "l"(p));
    return a;
}
__device__ __forceinline__ void ldsm_x4(uint32_t* r, uint32_t addr) {
    asm volatile("ldmatrix.sync.aligned.m8n8.x4.shared.b16 {%0,%1,%2,%3}, [%4];"
        : "=r"(r[0]), "=r"(r[1]), "=r"(r[2]), "=r"(r[3]) : "r"(addr));
}
__device__ __forceinline__ void ldsm_x2(uint32_t* r, uint32_t addr) {
    asm volatile("ldmatrix.sync.aligned.m8n8.x2.shared.b16 {%0,%1}, [%2];"
        : "=r"(r[0]), "=r"(r[1]) : "r"(addr));
}
__device__ __forceinline__ void mma_f16(float* d, const uint32_t* a, const uint32_t* b) {
    asm volatile("mma.sync.aligned.m16n8k16.row.col.f32.f16.f16.f32 "
        "{%0,%1,%2,%3}, {%4,%5,%6,%7}, {%8,%9}, {%0,%1,%2,%3};"
        : "+f"(d[0]), "+f"(d[1]), "+f"(d[2]), "+f"(d[3])
        : "r"(a[0]), "r"(a[1]), "r"(a[2]), "r"(a[3]), "r"(b[0]), "r"(b[1]));
}
__device__ __forceinline__ void cp16(uint32_t dst, const void* src) {
    asm volatile("cp.async.cg.shared.global [%0], [%1], 16;" :: "r"(dst), "l"(src));
}
__device__ __forceinline__ void cp16p(uint32_t dst, const void* src, bool pred) {
    int sz = pred ? 16 : 0;
    asm volatile("cp.async.cg.shared.global [%0], [%1], 16, %2;" :: "r"(dst), "l"(src), "r"(sz));
}

// ------------------------- weight prep -------------------------
__global__ void k_wsum(const float* __restrict__ opw, const float* __restrict__ opb) {
    int i = threadIdx.x;
    float s = 0.f;
    #pragma unroll 4
    for (int j = 0; j < HID; j++) s += opw[j * HID + i];
    g_wsum[i] = s;
    __shared__ float red[256];
    red[i] = opb[i];
    __syncthreads();
    for (int off = 128; off > 0; off >>= 1) {
        if (i < off) red[i] += red[i + off];
        __syncthreads();
    }
    if (i == 0) g_bsum = red[0];
}

// merged weight conversion: W1^T, W2^T, Wqk -> fp16 (+bias copy)
__global__ void k_prep_w(const float* __restrict__ W1, const float* __restrict__ W2,
                         const float* __restrict__ ipw, const float* __restrict__ ipb) {
    int idx = blockIdx.x * blockDim.x + threadIdx.x;
    if (idx < 32768) {
        int n = idx >> 7, k = idx & 127;
        g_w1[idx] = __float2half(W1[k * HID + n]);
    } else if (idx < 98304) {
        int j = idx - 32768;
        int n = j >> 8, k = j & 255;
        g_w2[j] = __float2half(W2[k * HID + n]);
    } else if (idx < 229376) {
        int j = idx - 98304;
        g_wqk[j] = __float2half(ipw[j]);
        if (j < QK_N) g_biasqk[j] = ipb[j];
    }
}

__global__ void k_prep_vw(const float* __restrict__ ipw, const float* __restrict__ ipb) {
    int idx = blockIdx.x * blockDim.x + threadIdx.x;
    if (idx >= HID * 4) return;
    int k = idx >> 2, h = idx & 3;
    float s = 0.f;
    #pragma unroll 8
    for (int d = 0; d < 64; d++)
        s += g_wsum[h * 64 + d] * ipw[(size_t)(512 + h * 64 + d) * HID + k];
    g_wv[k * 4 + h] = s;
    if (idx < 4) {
        float b = 0.f;
        for (int d = 0; d < 64; d++)
            b += g_wsum[idx * 64 + d] * ipb[512 + idx * 64 + d];
        g_bvw[idx] = b;
    }
}

__global__ void k_cvt_x(const float* __restrict__ x) {
    int idx = blockIdx.x * blockDim.x + threadIdx.x;   // one float2 -> half2
    if (idx >= N_NODES * IN_CH / 2) return;
    float2 v = ((const float2*)x)[idx];
    ((__half2*)g_x16)[idx] = __floats2half2_rn(v.x, v.y);
}

// ------------------------- degree / CSR build -------------------------
__global__ void k_zero_deg() {
    int i = blockIdx.x * blockDim.x + threadIdx.x;
    if (i < N_NODES) g_deg[i] = 0;
}
__global__ void k_count(const int* __restrict__ ei, int E1) {
    int e = blockIdx.x * blockDim.x + threadIdx.x;
    if (e >= E1) return;
    atomicAdd(&g_deg[ei[E1 + e]], 1);
}
__global__ void k_dinv() {
    int i = blockIdx.x * blockDim.x + threadIdx.x;
    if (i < N_NODES) g_dinv[i] = rsqrtf((float)(g_deg[i] + 1));
}
// 3-phase parallel exclusive scan of deg -> rowptr/cursor
__global__ void k_scanA() {
    int b = blockIdx.x, t = threadIdx.x;
    int i = b * 1024 + t;
    int v = (i < N_NODES) ? g_deg[i] : 0;
    int lane = t & 31, w = t >> 5;
    int x = v;
    #pragma unroll
    for (int o = 1; o < 32; o <<= 1) {
        int y = __shfl_up_sync(0xffffffffu, x, o);
        if (lane >= o) x += y;
    }
    __shared__ int ws[32];
    if (lane == 31) ws[w] = x;
    __syncthreads();
    if (w == 0) {
        int s = ws[lane];
        #pragma unroll
        for (int o = 1; o < 32; o <<= 1) {
            int y = __shfl_up_sync(0xffffffffu, s, o);
            if (lane >= o) s += y;
        }
        ws[lane] = s;
    }
    __syncthreads();
    int incl = x + (w > 0 ? ws[w - 1] : 0);
    if (i < N_NODES) g_cursor[i] = incl;   // temp: local inclusive scan
    if (t == 1023) g_bsums[b] = incl;
}
__global__ void k_scanB(int nblk) {
    __shared__ int sh[64];
    int t = threadIdx.x;
    int v = (t < nblk) ? g_bsums[t] : 0;
    sh[t] = v;
    __syncthreads();
    for (int o = 1; o < 64; o <<= 1) {
        int y = (t >= o) ? sh[t - o] : 0;
        __syncthreads();
        sh[t] += y;
        __syncthreads();
    }
    g_boff[t] = sh[t] - v;   // exclusive block offset
}
__global__ void k_scanC() {
    int b = blockIdx.x, t = threadIdx.x;
    int i = b * 1024 + t;
    if (i < N_NODES) {
        int inc = g_cursor[i] + g_boff[b];
        g_rowptr[i + 1] = inc;
        g_cursor[i] = inc - g_deg[i];
    }
    if (i == 0) g_rowptr[0] = 0;
}
__global__ void k_scatter(const int* __restrict__ ei, int E1) {
    int e = blockIdx.x * blockDim.x + threadIdx.x;
    if (e >= E1) return;
    int pos = atomicAdd(&g_cursor[ei[E1 + e]], 1);
    g_colsrc[pos] = ei[e];
}

// ------------------------- fp16 GEMM via mma.sync, cp.async double-buffered --------
// C[M,N] = A[M,K] @ Bt[N,K]^T + bias (fp32), output fp16.
#define STR 40                   // padded smem row stride (16-bit elems), 80B rows
#define TILE_B (128 * STR * 2)   // 10240 bytes per tile
#define BUF_B  (2 * TILE_B)      // A, B
#define GSM    (2 * BUF_B)       // double buffered: 40960 bytes
__global__ __launch_bounds__(256) void k_gemm(
    const __half* __restrict__ A, const __half* __restrict__ B,
    const float* __restrict__ bias, __half* __restrict__ Ch,
    int M, int N, int K, int ldc)
{
    extern __shared__ char smdyn[];
    uint32_t sb = smem_u32(smdyn);

    int tid = threadIdx.x;
    int lane = tid & 31, w = tid >> 5;
    int wm0 = (w >> 2) * 64, wn0 = (w & 3) * 32;
    int m0 = blockIdx.y * 128, n0 = blockIdx.x * 128;

    float acc[4][4][4];
    #pragma unroll
    for (int mt = 0; mt < 4; mt++)
        #pragma unroll
        for (int nt = 0; nt < 4; nt++)
            #pragma unroll
            for (int q = 0; q < 4; q++) acc[mt][nt][q] = 0.f;

    int r8 = lane & 7, sel = lane >> 3;
    uint32_t aoff[4], boff[4];
    #pragma unroll
    for (int mt = 0; mt < 4; mt++)
        aoff[mt] = ((wm0 + mt * 16 + (sel & 1) * 8 + r8) * STR + (sel >> 1) * 8) * 2;
    int selb = sel & 1;
    #pragma unroll
    for (int nt = 0; nt < 4; nt++)
        boff[nt] = ((wn0 + nt * 8 + r8) * STR + selb * 8) * 2;

    int nch = K >> 5;

    auto stage = [&](int ch, int buf) {
        int k0 = ch << 5;
        #pragma unroll
        for (int i = 0; i < 2; i++) {
            int lin = tid + i * 256;
            int row = lin >> 2, seg = lin & 3;
            uint32_t dst = sb + buf * BUF_B + row * (STR * 2) + seg * 16;
            int gr = m0 + row;
            bool ok = gr < M;
            int grc = ok ? gr : 0;
            int gn = n0 + row;   // N multiple of 128
            cp16p(dst, A + (size_t)grc * K + k0 + seg * 8, ok);
            cp16(dst + TILE_B, B + (size_t)gn * K + k0 + seg * 8);
        }
        asm volatile("cp.async.commit_group;" ::: "memory");
    };

    stage(0, 0);
    for (int ch = 0; ch < nch; ch++) {
        int buf = ch & 1;
        if (ch + 1 < nch) {
            stage(ch + 1, buf ^ 1);
            asm volatile("cp.async.wait_group 1;" ::: "memory");
        } else {
            asm volatile("cp.async.wait_group 0;" ::: "memory");
        }
        __syncthreads();
        uint32_t base = sb + buf * BUF_B;
        #pragma unroll
        for (int ks = 0; ks < 2; ks++) {
            uint32_t a[4][4], b[4][2];
            #pragma unroll
            for (int mt = 0; mt < 4; mt++)
                ldsm_x4(a[mt], base + aoff[mt] + ks * 32);
            #pragma unroll
            for (int nt = 0; nt < 4; nt++)
                ldsm_x2(b[nt], base + TILE_B + boff[nt] + ks * 32);
            #pragma unroll
            for (int mt = 0; mt < 4; mt++)
                #pragma unroll
                for (int nt = 0; nt < 4; nt++)
                    mma_f16(acc[mt][nt], a[mt], b[nt]);
        }
        __syncthreads();
    }

    // epilogue: fp32 bias, fp16 stores
    int g = lane >> 2, tg = lane & 3;
    #pragma unroll
    for (int mt = 0; mt < 4; mt++) {
        #pragma unroll
        for (int nt = 0; nt < 4; nt++) {
            int row = m0 + wm0 + mt * 16 + g;
            int col = n0 + wn0 + nt * 8 + tg * 2;
            float2 bv = *(const float2*)(bias + col);
            if (row < M)
                *(__half2*)(Ch + (size_t)row * ldc + col) =
                    __floats2half2_rn(acc[mt][nt][0] + bv.x, acc[mt][nt][1] + bv.y);
            if (row + 8 < M)
                *(__half2*)(Ch + (size_t)(row + 8) * ldc + col) =
                    __floats2half2_rn(acc[mt][nt][2] + bv.x, acc[mt][nt][3] + bv.y);
        }
    }
}

// ------------------------- CSR aggregation (fp16 gathers) -------------------------
// agg1: h = relu(D^-1/2 (A+I) D^-1/2 t), fp16 out
__global__ void k_agg1(const __half* __restrict__ tin) {
    int n = blockIdx.x;
    int t = threadIdx.x;                  // 64 threads, each owns 4 channels
    int beg = g_rowptr[n], end = g_rowptr[n + 1];
    const uint2* tv = (const uint2*)tin;  // row = 64 uint2 (512B)
    float a0 = 0.f, a1 = 0.f, a2 = 0.f, a3 = 0.f;
    #pragma unroll 4
    for (int j = beg; j < end; j++) {
        int s = g_colsrc[j];
        float w = g_dinv[s];
        uint2 v = tv[(size_t)s * 64 + t];
        float2 f01 = __half22float2(*(const __half2*)&v.x);
        float2 f23 = __half22float2(*(const __half2*)&v.y);
        a0 += w * f01.x; a1 += w * f01.y; a2 += w * f23.x; a3 += w * f23.y;
    }
    float d = g_dinv[n], d2 = d * d;
    uint2 sv = tv[(size_t)n * 64 + t];
    float2 s01 = __half22float2(*(const __half2*)&sv.x);
    float2 s23 = __half22float2(*(const __half2*)&sv.y);
    float r0 = fmaxf(d * a0 + d2 * s01.x, 0.f);
    float r1 = fmaxf(d * a1 + d2 * s01.y, 0.f);
    float r2 = fmaxf(d * a2 + d2 * s23.x, 0.f);
    float r3 = fmaxf(d * a3 + d2 * s23.y, 0.f);
    uint2 ho;
    *(__half2*)&ho.x = __floats2half2_rn(r0, r1);
    *(__half2*)&ho.y = __floats2half2_rn(r2, r3);
    ((uint2*)g_h16)[(size_t)n * 64 + t] = ho;
}

// agg2: z = D^-1/2 (A+I) D^-1/2 t; writes fp16 z + fused folded-V (vw = z.wv + bvw)
__global__ void k_agg2(const __half* __restrict__ tin) {
    int n = blockIdx.x;
    int t = threadIdx.x;
    int lane = t & 31, wrp = t >> 5;
    int beg = g_rowptr[n], end = g_rowptr[n + 1];
    const uint2* tv = (const uint2*)tin;
    float a0 = 0.f, a1 = 0.f, a2 = 0.f, a3 = 0.f;
    #pragma unroll 4
    for (int j = beg; j < end; j++) {
        int s = g_colsrc[j];
        float w = g_dinv[s];
        uint2 v = tv[(size_t)s * 64 + t];
        float2 f01 = __half22float2(*(const __half2*)&v.x);
        float2 f23 = __half22float2(*(const __half2*)&v.y);
        a0 += w * f01.x; a1 += w * f01.y; a2 += w * f23.x; a3 += w * f23.y;
    }
    float d = g_dinv[n], d2 = d * d;
    uint2 sv = tv[(size_t)n * 64 + t];
    float2 s01 = __half22float2(*(const __half2*)&sv.x);
    float2 s23 = __half22float2(*(const __half2*)&sv.y);
    float r0 = d * a0 + d2 * s01.x;
    float r1 = d * a1 + d2 * s01.y;
    float r2 = d * a2 + d2 * s23.x;
    float r3 = d * a3 + d2 * s23.y;
    uint2 zo;
    *(__half2*)&zo.x = __floats2half2_rn(r0, r1);
    *(__half2*)&zo.y = __floats2half2_rn(r2, r3);
    ((uint2*)g_z16)[(size_t)n * 64 + t] = zo;
    // folded V partials: channels t*4..t*4+3
    const float4* wv4 = (const float4*)g_wv;
    float4 w0 = wv4[t * 4], w1 = wv4[t * 4 + 1], w2 = wv4[t * 4 + 2], w3 = wv4[t * 4 + 3];
    float p0 = r0 * w0.x + r1 * w1.x + r2 * w2.x + r3 * w3.x;
    float p1 = r0 * w0.y + r1 * w1.y + r2 * w2.y + r3 * w3.y;
    float p2 = r0 * w0.z + r1 * w1.z + r2 * w2.z + r3 * w3.z;
    float p3 = r0 * w0.w + r1 * w1.w + r2 * w2.w + r3 * w3.w;
    #pragma unroll
    for (int m = 16; m > 0; m >>= 1) {
        p0 += __shfl_xor_sync(0xffffffffu, p0, m);
        p1 += __shfl_xor_sync(0xffffffffu, p1, m);
        p2 += __shfl_xor_sync(0xffffffffu, p2, m);
        p3 += __shfl_xor_sync(0xffffffffu, p3, m);
    }
    __shared__ float sp[2][4];
    if (lane == 0) {
        sp[wrp][0] = p0; sp[wrp][1] = p1; sp[wrp][2] = p2; sp[wrp][3] = p3;
    }
    __syncthreads();
    if (t < 4)
        g_vw[n * 4 + t] = sp[0][t] + sp[1][t] + g_bvw[t];
}

// ------------------------- per-node self scores -------------------------
__global__ void k_qkself() {
    int n = (blockIdx.x * blockDim.x + threadIdx.x) >> 5;
    int lane = threadIdx.x & 31;
    if (n >= N_NODES) return;
    const uint4* qk = (const uint4*)(g_qkvh + (size_t)n * QK_N);
    uint4 qv = qk[lane];        // Q[lane*8 .. +7]
    uint4 kv = qk[32 + lane];   // K[lane*8 .. +7]
    const __half2* qh = (const __half2*)&qv;
    const __half2* kh = (const __half2*)&kv;
    float d = 0.f;
    #pragma unroll
    for (int j = 0; j < 4; j++) {
        float2 a = __half22float2(qh[j]);
        float2 b = __half22float2(kh[j]);
        d += a.x * b.x + a.y * b.y;
    }
    #pragma unroll
    for (int m = 1; m <= 4; m <<= 1) d += __shfl_xor_sync(0xffffffffu, d, m);
    if ((lane & 7) == 0) g_qkself[n * 4 + (lane >> 3)] = d;
}

// ------------------------- per-prediction-edge attention -------------------------
__global__ void k_edge(const int* __restrict__ eip, float* __restrict__ out, int E2) {
    int w = (blockIdx.x * blockDim.x + threadIdx.x) >> 5;
    int lane = threadIdx.x & 31;
    if (w >= E2) return;
    int sp = eip[w];
    int dp = eip[E2 + w];
    const uint4* Qr = (const uint4*)(g_qkvh + (size_t)sp * QK_N);
    const uint4* Kr = (const uint4*)(g_qkvh + (size_t)dp * QK_N);
    uint4 qv = Qr[lane];        // Q(sp)[lane*8..]
    uint4 kv = Kr[32 + lane];   // K(dp)[lane*8..]
    const __half2* qh = (const __half2*)&qv;
    const __half2* kh = (const __half2*)&kv;
    float d = 0.f;
    #pragma unroll
    for (int j = 0; j < 4; j++) {
        float2 a = __half22float2(qh[j]);
        float2 b = __half22float2(kh[j]);
        d += a.x * b.x + a.y * b.y;
    }
    #pragma unroll
    for (int m = 1; m <= 4; m <<= 1) d += __shfl_xor_sync(0xffffffffu, d, m);
    float s0 = __shfl_sync(0xffffffffu, d, 0);
    float s1 = __shfl_sync(0xffffffffu, d, 8);
    float s2 = __shfl_sync(0xffffffffu, d, 16);
    float s3 = __shfl_sync(0xffffffffu, d, 24);
    if (lane == 0) {
        float sc[4] = { s0, s1, s2, s3 };     // cross scores q(sp).k(dp)
        const float* vws = g_vw + (size_t)sp * 4;
        const float* vwd = g_vw + (size_t)dp * 4;
        const float* qks = g_qkself + (size_t)sp * 4;
        float acc = g_bsum;
        #pragma unroll
        for (int h = 0; h < 4; h++) {
            float a = 1.f / (1.f + expf((sc[h] - qks[h]) * 0.125f));
            acc += a * vws[h] + (1.f - a) * vwd[h];
        }
        out[w] = 1.f / (1.f + expf(-acc));
    }
}

// ------------------------- launch -------------------------
extern "C" void kernel_launch(void* const* d_in, const int* in_sizes, int n_in,
                              void* d_out, int out_size) {
    const float* x   = (const float*)d_in[0];
    const int* ei    = (const int*)d_in[1];
    const int* eip   = (const int*)d_in[2];
    const float* W1  = (const float*)d_in[3];
    const float* b1  = (const float*)d_in[4];
    const float* W2  = (const float*)d_in[5];
    const float* b2  = (const float*)d_in[6];
    const float* ipw = (const float*)d_in[7];
    const float* ipb = (const float*)d_in[8];
    const float* opw = (const float*)d_in[9];
    const float* opb = (const float*)d_in[10];
    float* out       = (float*)d_out;

    int E1 = in_sizes[1] / 2;
    int E2 = in_sizes[2] / 2;

    static bool attr_set = false;
    if (!attr_set) {
        cudaFuncSetAttribute(k_gemm, cudaFuncAttributeMaxDynamicSharedMemorySize, GSM);
        attr_set = true;
    }

    float* pBqk;
    __half *pX, *pT, *pH, *pZ, *pQKV, *pW1, *pW2, *pWqk;
    cudaGetSymbolAddress((void**)&pX,   g_x16);
    cudaGetSymbolAddress((void**)&pT,   g_t16);
    cudaGetSymbolAddress((void**)&pH,   g_h16);
    cudaGetSymbolAddress((void**)&pZ,   g_z16);
    cudaGetSymbolAddress((void**)&pQKV, g_qkvh);
    cudaGetSymbolAddress((void**)&pW1,  g_w1);
    cudaGetSymbolAddress((void**)&pW2,  g_w2);
    cudaGetSymbolAddress((void**)&pWqk, g_wqk);
    cudaGetSymbolAddress((void**)&pBqk, g_biasqk);

    // weight prep + input conversion
    k_wsum<<<1, 256>>>(opw, opb);
    k_prep_w<<<896, 256>>>(W1, W2, ipw, ipb);
    k_prep_vw<<<4, 256>>>(ipw, ipb);
    k_cvt_x<<<(N_NODES * IN_CH / 2 + 255) / 256, 256>>>(x);

    // degree + CSR (parallel scan)
    k_zero_deg<<<(N_NODES + 255) / 256, 256>>>();
    k_count<<<(E1 + 255) / 256, 256>>>(ei, E1);
    k_dinv<<<(N_NODES + 255) / 256, 256>>>();
    int nblk = (N_NODES + 1023) / 1024;
    k_scanA<<<nblk, 1024>>>();
    k_scanB<<<1, 64>>>(nblk);
    k_scanC<<<nblk, 1024>>>();
    k_scatter<<<(E1 + 255) / 256, 256>>>(ei, E1);

    dim3 g1(HID / 128, (N_NODES + 127) / 128);
    dim3 g3(QK_N / 128, (N_NODES + 127) / 128);

    // GCN layer 1: t1 = x@W1+b1, h = relu(agg(t1))
    k_gemm<<<g1, 256, GSM>>>(pX, pW1, b1, pT, N_NODES, HID, IN_CH, HID);
    k_agg1<<<N_NODES, 64>>>(pT);

    // GCN layer 2: t2 = h@W2+b2, z = agg(t2) + fused vw
    k_gemm<<<g1, 256, GSM>>>(pH, pW2, b2, pT, N_NODES, HID, HID, HID);
    k_agg2<<<N_NODES, 64>>>(pT);

    // QK projection (512 cols)
    k_gemm<<<g3, 256, GSM>>>(pZ, pWqk, pBqk, pQKV, N_NODES, QK_N, HID, QK_N);

    // self scores, then per-edge attention
    k_qkself<<<(N_NODES * 32 + 255) / 256, 256>>>();
    k_edge<<<((size_t)E2 * 32 + 255) / 256, 256>>>(eip, out, E2);
}